// round 13
// baseline (speedup 1.0000x reference)
#include <cuda_runtime.h>
#include <cuda_fp16.h>
#include <cstdint>
#include <math.h>

#define DIM    1024
#define HEADS  16
#define HD     64
#define WIN    16
#define NTOK   16384   // B*S
#define NWIN   1024

// Scratch (allocation-free rule: __device__ globals)
__device__ __align__(16) __half g_attnh[NTOK * DIM];
__device__ __align__(16) __half g_xh[NTOK * DIM];
__device__ __align__(16) __half g_wqh[DIM * DIM];   // rows permuted (rope pairing)
__device__ __align__(16) __half g_wkh[DIM * DIM];   // rows permuted (rope pairing)
__device__ __align__(16) __half g_wvh[DIM * DIM];
__device__ __align__(16) __half g_woh[DIM * DIM];

// ---------------------------------------------------------------------------
// helpers
// ---------------------------------------------------------------------------
__device__ __forceinline__ uint32_t smem_u32(const void* p) {
    uint32_t a;
    asm("{ .reg .u64 t; cvta.to.shared.u64 t, %1; cvt.u32.u64 %0, t; }"
        : "=r"(a) : "l"(p));
    return a;
}
__device__ __forceinline__ void cp_async16(uint32_t dst, const void* src) {
    asm volatile("cp.async.cg.shared.global [%0], [%1], 16;"
                 :: "r"(dst), "l"(src) : "memory");
}
__device__ __forceinline__ void cp_commit() {
    asm volatile("cp.async.commit_group;" ::: "memory");
}
template <int N>
__device__ __forceinline__ void cp_wait() {
    asm volatile("cp.async.wait_group %0;" :: "n"(N) : "memory");
}
__device__ __forceinline__ void ldsm_x4(uint32_t r[4], uint32_t addr) {
    asm volatile("ldmatrix.sync.aligned.m8n8.x4.shared.b16 {%0,%1,%2,%3}, [%4];"
                 : "=r"(r[0]), "=r"(r[1]), "=r"(r[2]), "=r"(r[3]) : "r"(addr));
}
__device__ __forceinline__ void ldsm_x4_trans(uint32_t r[4], uint32_t addr) {
    asm volatile("ldmatrix.sync.aligned.m8n8.x4.trans.shared.b16 {%0,%1,%2,%3}, [%4];"
                 : "=r"(r[0]), "=r"(r[1]), "=r"(r[2]), "=r"(r[3]) : "r"(addr));
}
__device__ __forceinline__ void mma_f16_16x8x16(float c[4],
                                                uint32_t a0, uint32_t a1,
                                                uint32_t a2, uint32_t a3,
                                                uint32_t b0, uint32_t b1) {
    asm volatile(
        "mma.sync.aligned.m16n8k16.row.col.f32.f16.f16.f32 "
        "{%0,%1,%2,%3}, {%4,%5,%6,%7}, {%8,%9}, {%0,%1,%2,%3};"
        : "+f"(c[0]), "+f"(c[1]), "+f"(c[2]), "+f"(c[3])
        : "r"(a0), "r"(a1), "r"(a2), "r"(a3), "r"(b0), "r"(b1));
}
__device__ __forceinline__ uint32_t h2u(__half2 h) { return *(uint32_t*)&h; }

// ---------------------------------------------------------------------------
// Fused QKV GEMM + fused-RoPE epilogue + windowed attention.
// CTA tile 128 tokens x 128 cols (= 8 windows x 2 heads). 512 threads,
// 16 warps of 32x32 GEMM tiles; attention: 1 warp per (window, head).
// wq/wk rows are pre-permuted so that output cols (2p, 2p+1) = original
// (p, p+32) within each head -> rope is a register-level 2x2 rotation in the
// q/k epilogues (fp32, one fp16 rounding). Scores are permutation-invariant.
// ---------------------------------------------------------------------------
constexpr int FBM = 128, FBN = 128, FBK = 64;
constexpr int FROWB  = 144;                     // staging row bytes
constexpr int FA_SZ  = FBM * FROWB;             // 18432
constexpr int FB_SZ  = FBN * FROWB;             // 18432
constexpr int FSTG   = FA_SZ + FB_SZ;           // 36864
constexpr int TSTRIDE = 136;                    // tile row stride (halves)
constexpr int TILE_SZ = FBM * TSTRIDE * 2;      // 34816
constexpr int OFF_Q  = 2 * FSTG;                // 73728
constexpr int OFF_K  = OFF_Q + TILE_SZ;         // 108544
constexpr int OFF_V  = OFF_K + TILE_SZ;         // 143360
constexpr int OFF_CS = OFF_V + TILE_SZ;         // 178176
constexpr int OFF_SN = OFF_CS + 2048;
constexpr int FSMEM  = OFF_SN + 2048;           // 182272

__global__ __launch_bounds__(512, 1)
void fused_qkv_attn(const float* __restrict__ rope)
{
    extern __shared__ char smc[];
    const uint32_t sb = smem_u32(smc);
    float* cs = (float*)(smc + OFF_CS);
    float* sn = (float*)(smc + OFF_SN);

    const int tid  = threadIdx.x;
    const int lane = tid & 31, wid = tid >> 5;
    const int g = lane >> 2, tid4 = lane & 3;
    const int warpM = wid & 3, warpN = wid >> 2;
    const int bm = blockIdx.y * FBM, bn = blockIdx.x * FBN;

    sincosf(rope[tid], &sn[tid], &cs[tid]);   // [pos][freq] = [16][32]

    // staging mapping: rows srow, srow+64; chunk acc8 (8 halves)
    const int srow = tid >> 3, acc8 = tid & 7;
    const __half* Ag = g_xh + (size_t)(bm + srow) * DIM + acc8 * 8;
    const uint32_t sdA = sb + srow * FROWB + acc8 * 16;
    const uint32_t sdB = sb + FA_SZ + srow * FROWB + acc8 * 16;

    auto stage = [&](int s, int kt, const __half* Bw) {
        const uint32_t so = s * FSTG;
        const size_t ko = (size_t)kt * FBK;
        cp_async16(sdA + so,              Ag + ko);
        cp_async16(sdA + so + 64 * FROWB, Ag + ko + (size_t)64 * DIM);
        const __half* Bg = Bw + (size_t)(bn + srow) * DIM + acc8 * 8;
        cp_async16(sdB + so,              Bg + ko);
        cp_async16(sdB + so + 64 * FROWB, Bg + ko + (size_t)64 * DIM);
        cp_commit();
    };

    const uint32_t aoff = (warpM * 32 + (lane & 15)) * FROWB + ((lane >> 4) << 4);
    const uint32_t boff = FA_SZ + (warpN * 32 + (lane & 15)) * FROWB + ((lane >> 4) << 4);

    // ---- 3 GEMM phases: q, k, v ----
    #pragma unroll 1
    for (int ph = 0; ph < 3; ph++) {
        const __half* Bw = (ph == 0) ? g_wqh : (ph == 1) ? g_wkh : g_wvh;

        float acc[2][4][4];
        #pragma unroll
        for (int i = 0; i < 2; i++)
            #pragma unroll
            for (int j = 0; j < 4; j++)
                #pragma unroll
                for (int q = 0; q < 4; q++)
                    acc[i][j][q] = 0.f;

        stage(0, 0, Bw);
        int s = 0;
        #pragma unroll 1
        for (int kt = 0; kt < DIM / FBK; kt++) {
            cp_wait<0>();
            __syncthreads();
            if (kt + 1 < DIM / FBK) stage(s ^ 1, kt + 1, Bw);

            const uint32_t ab = sb + s * FSTG + aoff;
            const uint32_t bb = sb + s * FSTG + boff;
            #pragma unroll
            for (int ks = 0; ks < 4; ks++) {
                uint32_t af[2][4], bf[2][4];
                ldsm_x4(af[0], ab + ks * 32);
                ldsm_x4(af[1], ab + 16 * FROWB + ks * 32);
                ldsm_x4(bf[0], bb + ks * 32);
                ldsm_x4(bf[1], bb + 16 * FROWB + ks * 32);
                #pragma unroll
                for (int mt = 0; mt < 2; mt++)
                    #pragma unroll
                    for (int p = 0; p < 2; p++) {
                        mma_f16_16x8x16(acc[mt][2 * p],
                                        af[mt][0], af[mt][1], af[mt][2], af[mt][3],
                                        bf[p][0], bf[p][2]);
                        mma_f16_16x8x16(acc[mt][2 * p + 1],
                                        af[mt][0], af[mt][1], af[mt][2], af[mt][3],
                                        bf[p][1], bf[p][3]);
                    }
            }
            s ^= 1;
        }

        // epilogue: rope (q,k phases) in fp32 regs, then -> fp16 smem tile.
        // Thread holds cols (ncol, ncol+1) = permuted pair (p, p+32) of head.
        const bool dorope = (ph < 2);
        __half* tp = (__half*)(smc + OFF_Q + ph * TILE_SZ);
        #pragma unroll
        for (int mt = 0; mt < 2; mt++) {
            const int r0 = warpM * 32 + mt * 16 + g;
            const int pos0 = r0 & 15;          // window position of row r0
            const int pos1 = (r0 + 8) & 15;    // window position of row r0+8
            #pragma unroll
            for (int j = 0; j < 4; j++) {
                const int ncol = warpN * 32 + (j >> 1) * 16 + (j & 1) * 8 + 2 * tid4;
                float a0 = acc[mt][j][0], a1 = acc[mt][j][1];
                float a2 = acc[mt][j][2], a3 = acc[mt][j][3];
                if (dorope) {
                    const int p = (ncol & 63) >> 1;   // freq index within head
                    const float c0 = cs[pos0 * 32 + p], s0 = sn[pos0 * 32 + p];
                    const float c1 = cs[pos1 * 32 + p], s1 = sn[pos1 * 32 + p];
                    const float t0 = a0 * c0 - a1 * s0;
                    const float t1 = a0 * s0 + a1 * c0;
                    const float t2 = a2 * c1 - a3 * s1;
                    const float t3 = a2 * s1 + a3 * c1;
                    a0 = t0; a1 = t1; a2 = t2; a3 = t3;
                }
                *(__half2*)(tp + r0 * TSTRIDE + ncol)       = __floats2half2_rn(a0, a1);
                *(__half2*)(tp + (r0 + 8) * TSTRIDE + ncol) = __floats2half2_rn(a2, a3);
            }
        }
    }
    __syncthreads();

    // ---- attention: 1 warp per (window, head) ----
    // q/k are stored in permuted dim order; scores are invariant since both
    // use the same permutation. V is unpermuted.
    {
        const int wi = wid & 7, head = wid >> 3;
        const int r16 = lane & 15, hc = (lane >> 4) * 8;
        const uint32_t base = sb + ((uint32_t)((wi * 16 + r16) * TSTRIDE + head * 64 + hc) << 1);
        const uint32_t qb = base + OFF_Q;
        const uint32_t kb = base + OFF_K;
        const uint32_t vb = base + OFF_V;

        float sc[2][4] = {};
        #pragma unroll
        for (int ks = 0; ks < 4; ks++) {
            uint32_t aq[4], bk[4];
            ldsm_x4(aq, qb + ks * 32);
            ldsm_x4(bk, kb + ks * 32);
            mma_f16_16x8x16(sc[0], aq[0], aq[1], aq[2], aq[3], bk[0], bk[2]);
            mma_f16_16x8x16(sc[1], aq[0], aq[1], aq[2], aq[3], bk[1], bk[3]);
        }
        #pragma unroll
        for (int t2 = 0; t2 < 2; t2++)
            #pragma unroll
            for (int q = 0; q < 4; q++)
                sc[t2][q] *= 0.125f;

        float mA = fmaxf(fmaxf(sc[0][0], sc[0][1]), fmaxf(sc[1][0], sc[1][1]));
        float mB = fmaxf(fmaxf(sc[0][2], sc[0][3]), fmaxf(sc[1][2], sc[1][3]));
        mA = fmaxf(mA, __shfl_xor_sync(0xffffffffu, mA, 1));
        mA = fmaxf(mA, __shfl_xor_sync(0xffffffffu, mA, 2));
        mB = fmaxf(mB, __shfl_xor_sync(0xffffffffu, mB, 1));
        mB = fmaxf(mB, __shfl_xor_sync(0xffffffffu, mB, 2));
        float eA0 = expf(sc[0][0] - mA), eA1 = expf(sc[0][1] - mA);
        float eA2 = expf(sc[1][0] - mA), eA3 = expf(sc[1][1] - mA);
        float eB0 = expf(sc[0][2] - mB), eB1 = expf(sc[0][3] - mB);
        float eB2 = expf(sc[1][2] - mB), eB3 = expf(sc[1][3] - mB);
        float sA = eA0 + eA1 + eA2 + eA3;
        float sB = eB0 + eB1 + eB2 + eB3;
        sA += __shfl_xor_sync(0xffffffffu, sA, 1);
        sA += __shfl_xor_sync(0xffffffffu, sA, 2);
        sB += __shfl_xor_sync(0xffffffffu, sB, 1);
        sB += __shfl_xor_sync(0xffffffffu, sB, 2);
        const float iA = 1.f / sA, iB = 1.f / sB;

        const uint32_t p0 = h2u(__floats2half2_rn(eA0 * iA, eA1 * iA));
        const uint32_t p1 = h2u(__floats2half2_rn(eB0 * iB, eB1 * iB));
        const uint32_t p2 = h2u(__floats2half2_rn(eA2 * iA, eA3 * iA));
        const uint32_t p3 = h2u(__floats2half2_rn(eB2 * iB, eB3 * iB));

        float o[8][4] = {};
        #pragma unroll
        for (int nt = 0; nt < 4; nt++) {
            uint32_t bv[4];
            ldsm_x4_trans(bv, vb + nt * 32);
            mma_f16_16x8x16(o[2 * nt],     p0, p1, p2, p3, bv[0], bv[1]);
            mma_f16_16x8x16(o[2 * nt + 1], p0, p1, p2, p3, bv[2], bv[3]);
        }

        const size_t orow = (size_t)(bm + wi * 16 + g);
        const int col0 = bn + head * 64;
        #pragma unroll
        for (int nt = 0; nt < 4; nt++)
            #pragma unroll
            for (int sub = 0; sub < 2; sub++) {
                const int j = 2 * nt + sub;
                const int col = col0 + nt * 16 + sub * 8 + 2 * tid4;
                *(__half2*)(g_attnh + orow * DIM + col) =
                    __floats2half2_rn(o[j][0], o[j][1]);
                *(__half2*)(g_attnh + (orow + 8) * DIM + col) =
                    __floats2half2_rn(o[j][2], o[j][3]);
            }
    }
}

// ---------------------------------------------------------------------------
// WO GEMM: CTA 256x128, BK=64, 512 threads, 16 warps of 64x32.
// ---------------------------------------------------------------------------
constexpr int BM = 256, BN = 128, BK = 64;
constexpr int ROWB   = 144;
constexpr int A_SZ   = BM * ROWB;
constexpr int B_SZ   = BN * ROWB;
constexpr int STG_SZ = A_SZ + B_SZ;
constexpr int GSMEM  = 2 * STG_SZ;          // 110592

__global__ __launch_bounds__(512, 1)
void gemm_wo(float* __restrict__ Cout)
{
    extern __shared__ uint32_t sm[];
    const uint32_t sbu = smem_u32(sm);
    const __half* A = g_attnh;
    const __half* B = g_woh;

    const int tid  = threadIdx.x;
    const int lane = tid & 31, wid = tid >> 5;
    const int g = lane >> 2, tid4 = lane & 3;
    const int warpM = wid & 3;
    const int warpN = wid >> 2;
    const int bm = blockIdx.y * BM, bn = blockIdx.x * BN;

    const int arow = tid >> 3, acc8 = tid & 7;
    const __half* Ag = A + (size_t)(bm + arow) * DIM + acc8 * 8;
    const __half* Bg = B + (size_t)(bn + arow) * DIM + acc8 * 8;
    const uint32_t sdA = sbu + arow * ROWB + acc8 * 16;
    const uint32_t sdB = sbu + A_SZ + arow * ROWB + acc8 * 16;

    auto stage = [&](int s, int kt) {
        const uint32_t so = s * STG_SZ;
        const size_t ko = (size_t)kt * BK;
        #pragma unroll
        for (int i = 0; i < 4; i++)
            cp_async16(sdA + so + i * 64 * ROWB, Ag + ko + (size_t)(64 * i) * DIM);
        #pragma unroll
        for (int i = 0; i < 2; i++)
            cp_async16(sdB + so + i * 64 * ROWB, Bg + ko + (size_t)(64 * i) * DIM);
    };

    const uint32_t aoff = (warpM * 64 + (lane & 15)) * ROWB + ((lane >> 4) << 4);
    const uint32_t boff = A_SZ + (warpN * 32 + (lane & 15)) * ROWB + ((lane >> 4) << 4);

    float acc[4][4][4];
    #pragma unroll
    for (int i = 0; i < 4; i++)
        #pragma unroll
        for (int j = 0; j < 4; j++)
            #pragma unroll
            for (int q = 0; q < 4; q++)
                acc[i][j][q] = 0.f;

    stage(0, 0); cp_commit();

    const int NKT = DIM / BK;
    int s = 0;
    for (int kt = 0; kt < NKT; kt++) {
        cp_wait<0>();
        __syncthreads();
        if (kt + 1 < NKT) { stage(s ^ 1, kt + 1); cp_commit(); }

        const uint32_t ab = sbu + s * STG_SZ + aoff;
        const uint32_t bb = sbu + s * STG_SZ + boff;
        #pragma unroll
        for (int ks = 0; ks < 4; ks++) {
            uint32_t af[4][4], bf[2][4];
            #pragma unroll
            for (int mt = 0; mt < 4; mt++)
                ldsm_x4(af[mt], ab + mt * 16 * ROWB + ks * 32);
            #pragma unroll
            for (int p = 0; p < 2; p++)
                ldsm_x4(bf[p], bb + p * 16 * ROWB + ks * 32);
            #pragma unroll
            for (int mt = 0; mt < 4; mt++)
                #pragma unroll
                for (int p = 0; p < 2; p++) {
                    mma_f16_16x8x16(acc[mt][2 * p],
                                    af[mt][0], af[mt][1], af[mt][2], af[mt][3],
                                    bf[p][0], bf[p][2]);
                    mma_f16_16x8x16(acc[mt][2 * p + 1],
                                    af[mt][0], af[mt][1], af[mt][2], af[mt][3],
                                    bf[p][1], bf[p][3]);
                }
        }
        s ^= 1;
    }

    #pragma unroll
    for (int mt = 0; mt < 4; mt++) {
        const int r0 = bm + warpM * 64 + mt * 16 + g;
        #pragma unroll
        for (int j = 0; j < 4; j++) {
            const int ncol = bn + warpN * 32 + (j >> 1) * 16 + (j & 1) * 8;
            const float* a = acc[mt][j];
            *(float2*)(Cout + (size_t)r0 * DIM + ncol + 2 * tid4) =
                make_float2(a[0], a[1]);
            *(float2*)(Cout + (size_t)(r0 + 8) * DIM + ncol + 2 * tid4) =
                make_float2(a[2], a[3]);
        }
    }
}

// ---------------------------------------------------------------------------
// fp32 -> fp16 prepass: z 0..3 = quarters of x, z 4..7 = weights.
// wq (z=4) and wk (z=5) rows are PERMUTED: dst row n <- src row orig(n),
// where within each head (64 rows): orig(2p) = p, orig(2p+1) = p + 32.
// ---------------------------------------------------------------------------
__global__ void prep(const float4* __restrict__ x,
                     const float4* __restrict__ w0, const float4* __restrict__ w1,
                     const float4* __restrict__ w2, const float4* __restrict__ w3)
{
    const int z = blockIdx.z;
    if (z < 4) {
        const int quarter = NTOK * DIM / 16;
        const float4* src = x + (size_t)z * quarter;
        uint2* dst = (uint2*)g_xh + (size_t)z * quarter;
        int i = blockIdx.x * blockDim.x + threadIdx.x;
        const int stride = gridDim.x * blockDim.x;
        for (; i < quarter; i += stride) {
            float4 v = src[i];
            __half2 lo = __floats2half2_rn(v.x, v.y);
            __half2 hi = __floats2half2_rn(v.z, v.w);
            dst[i] = make_uint2(*(uint32_t*)&lo, *(uint32_t*)&hi);
        }
    } else {
        const float4* src = (z == 4) ? w0 : (z == 5) ? w1 : (z == 6) ? w2 : w3;
        uint2* dst = (uint2*)((z == 4) ? g_wqh : (z == 5) ? g_wkh
                            : (z == 6) ? g_wvh : g_woh);
        const bool permute = (z == 4 || z == 5);
        const int n4 = DIM * DIM / 4;
        int i = blockIdx.x * blockDim.x + threadIdx.x;
        const int stride = gridDim.x * blockDim.x;
        for (; i < n4; i += stride) {
            int si = i;
            if (permute) {
                const int row = i >> 8;            // DIM/4 = 256 float4 per row
                const int c4  = i & 255;
                const int h = row >> 6, m = row & 63;
                const int orig = (h << 6) + ((m & 1) ? 32 : 0) + (m >> 1);
                si = (orig << 8) + c4;
            }
            float4 v = src[si];
            __half2 lo = __floats2half2_rn(v.x, v.y);
            __half2 hi = __floats2half2_rn(v.z, v.w);
            dst[i] = make_uint2(*(uint32_t*)&lo, *(uint32_t*)&hi);
        }
    }
}

// ---------------------------------------------------------------------------
extern "C" void kernel_launch(void* const* d_in, const int* in_sizes, int n_in,
                              void* d_out, int out_size)
{
    const float* x    = (const float*)d_in[0];
    const float* rope = (const float*)d_in[1];
    const float* wq   = (const float*)d_in[2];
    const float* wk   = (const float*)d_in[3];
    const float* wv   = (const float*)d_in[4];
    const float* wo   = (const float*)d_in[5];
    float* out        = (float*)d_out;

    cudaFuncSetAttribute(fused_qkv_attn, cudaFuncAttributeMaxDynamicSharedMemorySize, FSMEM);
    cudaFuncSetAttribute(gemm_wo,        cudaFuncAttributeMaxDynamicSharedMemorySize, GSMEM);

    prep<<<dim3(256, 1, 8), 256>>>((const float4*)x, (const float4*)wq,
                                   (const float4*)wk, (const float4*)wv,
                                   (const float4*)wo);

    fused_qkv_attn<<<dim3(DIM / FBN, NTOK / FBM), 512, FSMEM>>>(rope);

    gemm_wo<<<dim3(DIM / BN, NTOK / BM), 512, GSMEM>>>(out);
}

// round 14
// speedup vs baseline: 1.1479x; 1.1479x over previous
#include <cuda_runtime.h>
#include <cuda_fp16.h>
#include <cstdint>
#include <math.h>

#define DIM    1024
#define HEADS  16
#define HD     64
#define WIN    16
#define NTOK   16384   // B*S
#define NWIN   1024

// Scratch (allocation-free rule: __device__ globals)
__device__ __align__(16) __half g_attnh[NTOK * DIM];
__device__ __align__(16) __half g_xh[NTOK * DIM];
__device__ __align__(16) __half g_wqh[DIM * DIM];
__device__ __align__(16) __half g_wkh[DIM * DIM];
__device__ __align__(16) __half g_wvh[DIM * DIM];
__device__ __align__(16) __half g_woh[DIM * DIM];

// ---------------------------------------------------------------------------
// helpers
// ---------------------------------------------------------------------------
__device__ __forceinline__ uint32_t smem_u32(const void* p) {
    uint32_t a;
    asm("{ .reg .u64 t; cvta.to.shared.u64 t, %1; cvt.u32.u64 %0, t; }"
        : "=r"(a) : "l"(p));
    return a;
}
__device__ __forceinline__ void cp_async16(uint32_t dst, const void* src) {
    asm volatile("cp.async.cg.shared.global [%0], [%1], 16;"
                 :: "r"(dst), "l"(src) : "memory");
}
__device__ __forceinline__ void cp_commit() {
    asm volatile("cp.async.commit_group;" ::: "memory");
}
template <int N>
__device__ __forceinline__ void cp_wait() {
    asm volatile("cp.async.wait_group %0;" :: "n"(N) : "memory");
}
__device__ __forceinline__ void ldsm_x4(uint32_t r[4], uint32_t addr) {
    asm volatile("ldmatrix.sync.aligned.m8n8.x4.shared.b16 {%0,%1,%2,%3}, [%4];"
                 : "=r"(r[0]), "=r"(r[1]), "=r"(r[2]), "=r"(r[3]) : "r"(addr));
}
__device__ __forceinline__ void ldsm_x4_trans(uint32_t r[4], uint32_t addr) {
    asm volatile("ldmatrix.sync.aligned.m8n8.x4.trans.shared.b16 {%0,%1,%2,%3}, [%4];"
                 : "=r"(r[0]), "=r"(r[1]), "=r"(r[2]), "=r"(r[3]) : "r"(addr));
}
__device__ __forceinline__ void mma_f16_16x8x16(float c[4],
                                                uint32_t a0, uint32_t a1,
                                                uint32_t a2, uint32_t a3,
                                                uint32_t b0, uint32_t b1) {
    asm volatile(
        "mma.sync.aligned.m16n8k16.row.col.f32.f16.f16.f32 "
        "{%0,%1,%2,%3}, {%4,%5,%6,%7}, {%8,%9}, {%0,%1,%2,%3};"
        : "+f"(c[0]), "+f"(c[1]), "+f"(c[2]), "+f"(c[3])
        : "r"(a0), "r"(a1), "r"(a2), "r"(a3), "r"(b0), "r"(b1));
}
__device__ __forceinline__ void h8f(const uint4 u, float f[8]) {
    float2 a = __half22float2(*(const __half2*)&u.x);
    float2 b = __half22float2(*(const __half2*)&u.y);
    float2 c = __half22float2(*(const __half2*)&u.z);
    float2 d = __half22float2(*(const __half2*)&u.w);
    f[0]=a.x; f[1]=a.y; f[2]=b.x; f[3]=b.y; f[4]=c.x; f[5]=c.y; f[6]=d.x; f[7]=d.y;
}
__device__ __forceinline__ uint4 f8h(const float f[8]) {
    __half2 a = __floats2half2_rn(f[0], f[1]);
    __half2 b = __floats2half2_rn(f[2], f[3]);
    __half2 c = __floats2half2_rn(f[4], f[5]);
    __half2 d = __floats2half2_rn(f[6], f[7]);
    return make_uint4(*(uint32_t*)&a, *(uint32_t*)&b, *(uint32_t*)&c, *(uint32_t*)&d);
}
__device__ __forceinline__ uint32_t h2u(__half2 h) { return *(uint32_t*)&h; }

// ---------------------------------------------------------------------------
// Fused QKV GEMM + RoPE + windowed attention (R9 structure).
// Staging buffers use exact 128B rows with SW128 XOR swizzle:
//   chunk' = chunk ^ (row & 7)   (16B chunks, 8 per row)
// -> conflict-free cp.async stores AND conflict-free ldmatrix loads.
// CTA tile 128 tokens x 128 cols (= 8 windows x 2 heads). 512 threads,
// 16 warps of 32x32 GEMM tiles; attention: 1 warp per (window, head).
// ---------------------------------------------------------------------------
constexpr int FBM = 128, FBN = 128, FBK = 64;
constexpr int FROWB  = 128;                     // staging row bytes (swizzled)
constexpr int FA_SZ  = FBM * FROWB;             // 16384
constexpr int FB_SZ  = FBN * FROWB;             // 16384
constexpr int FSTG   = FA_SZ + FB_SZ;           // 32768
constexpr int TSTRIDE = 136;                    // q/k/v tile row stride (halves)
constexpr int TILE_SZ = FBM * TSTRIDE * 2;      // 34816
constexpr int OFF_Q  = 2 * FSTG;                // 65536
constexpr int OFF_K  = OFF_Q + TILE_SZ;         // 100352
constexpr int OFF_V  = OFF_K + TILE_SZ;         // 135168
constexpr int OFF_CS = OFF_V + TILE_SZ;         // 169984
constexpr int OFF_SN = OFF_CS + 2048;
constexpr int FSMEM  = OFF_SN + 2048;           // 174080

__global__ __launch_bounds__(512, 1)
void fused_qkv_attn(const float* __restrict__ rope)
{
    extern __shared__ char smc[];
    const uint32_t sb = smem_u32(smc);
    float* cs = (float*)(smc + OFF_CS);
    float* sn = (float*)(smc + OFF_SN);

    const int tid  = threadIdx.x;
    const int lane = tid & 31, wid = tid >> 5;
    const int g = lane >> 2, tid4 = lane & 3;
    const int warpM = wid & 3, warpN = wid >> 2;
    const int bm = blockIdx.y * FBM, bn = blockIdx.x * FBN;

    sincosf(rope[tid], &sn[tid], &cs[tid]);   // [pos][freq] = [16][32]

    // staging mapping: rows srow, srow+64; chunk acc8 (16B). XOR swizzle.
    const int srow = tid >> 3, acc8 = tid & 7;
    const int swc  = acc8 ^ (srow & 7);           // (srow+64)&7 == srow&7
    const __half* Ag = g_xh + (size_t)(bm + srow) * DIM + acc8 * 8;
    const uint32_t sdA = sb + srow * FROWB + swc * 16;
    const uint32_t sdB = sb + FA_SZ + srow * FROWB + swc * 16;

    auto stage = [&](int s, int kt, const __half* Bw) {
        const uint32_t so = s * FSTG;
        const size_t ko = (size_t)kt * FBK;
        cp_async16(sdA + so,              Ag + ko);
        cp_async16(sdA + so + 64 * FROWB, Ag + ko + (size_t)64 * DIM);
        const __half* Bg = Bw + (size_t)(bn + srow) * DIM + acc8 * 8;
        cp_async16(sdB + so,              Bg + ko);
        cp_async16(sdB + so + 64 * FROWB, Bg + ko + (size_t)64 * DIM);
        cp_commit();
    };

    // ldmatrix bases: per-lane row; chunk is XOR-swizzled per ks in the loop.
    const int xrow = lane & 7;                    // (row & 7) for this lane
    const int hc8  = lane >> 4;                   // 16B-chunk half-select
    const uint32_t arow = sb + (uint32_t)(warpM * 32 + (lane & 15)) * FROWB;
    const uint32_t brow = sb + FA_SZ + (uint32_t)(warpN * 32 + (lane & 15)) * FROWB;

    // ---- 3 GEMM phases: q, k, v ----
    #pragma unroll 1
    for (int ph = 0; ph < 3; ph++) {
        const __half* Bw = (ph == 0) ? g_wqh : (ph == 1) ? g_wkh : g_wvh;

        float acc[2][4][4];
        #pragma unroll
        for (int i = 0; i < 2; i++)
            #pragma unroll
            for (int j = 0; j < 4; j++)
                #pragma unroll
                for (int q = 0; q < 4; q++)
                    acc[i][j][q] = 0.f;

        stage(0, 0, Bw);
        int s = 0;
        #pragma unroll 1
        for (int kt = 0; kt < DIM / FBK; kt++) {
            cp_wait<0>();
            __syncthreads();
            if (kt + 1 < DIM / FBK) stage(s ^ 1, kt + 1, Bw);

            const uint32_t so = s * FSTG;
            #pragma unroll
            for (int ks = 0; ks < 4; ks++) {
                const uint32_t ac = (uint32_t)(((ks * 2 + hc8) ^ xrow) << 4);
                uint32_t af[2][4], bf[2][4];
                ldsm_x4(af[0], arow + so + ac);
                ldsm_x4(af[1], arow + so + 16 * FROWB + ac);   // (row+16)&7 same
                ldsm_x4(bf[0], brow + so + ac);
                ldsm_x4(bf[1], brow + so + 16 * FROWB + ac);
                #pragma unroll
                for (int mt = 0; mt < 2; mt++)
                    #pragma unroll
                    for (int p = 0; p < 2; p++) {
                        mma_f16_16x8x16(acc[mt][2 * p],
                                        af[mt][0], af[mt][1], af[mt][2], af[mt][3],
                                        bf[p][0], bf[p][2]);
                        mma_f16_16x8x16(acc[mt][2 * p + 1],
                                        af[mt][0], af[mt][1], af[mt][2], af[mt][3],
                                        bf[p][1], bf[p][3]);
                    }
            }
            s ^= 1;
        }

        // epilogue: acc -> fp16 smem tile (warp-private region, no barrier)
        __half* tp = (__half*)(smc + OFF_Q + ph * TILE_SZ);
        #pragma unroll
        for (int mt = 0; mt < 2; mt++) {
            const int r0 = warpM * 32 + mt * 16 + g;
            #pragma unroll
            for (int j = 0; j < 4; j++) {
                const int ncol = warpN * 32 + (j >> 1) * 16 + (j & 1) * 8 + 2 * tid4;
                *(__half2*)(tp + r0 * TSTRIDE + ncol) =
                    __floats2half2_rn(acc[mt][j][0], acc[mt][j][1]);
                *(__half2*)(tp + (r0 + 8) * TSTRIDE + ncol) =
                    __floats2half2_rn(acc[mt][j][2], acc[mt][j][3]);
            }
        }
    }
    __syncthreads();

    // ---- RoPE in-place on q and k tiles ----
    {
        const int t  = tid >> 2;            // token row 0..127
        const int jq = (tid & 3) * 8;       // freq start
        const int pos = t & 15;
        #pragma unroll
        for (int tl = 0; tl < 2; tl++) {
            __half* tb = (__half*)(smc + (tl ? OFF_K : OFF_Q));
            #pragma unroll
            for (int h = 0; h < 2; h++) {
                __half* row = tb + t * TSTRIDE + h * 64;
                float lo[8], hi[8], nl[8], nh[8];
                h8f(*(uint4*)(row + jq), lo);
                h8f(*(uint4*)(row + 32 + jq), hi);
                #pragma unroll
                for (int j = 0; j < 8; j++) {
                    const float C_ = cs[pos * 32 + jq + j];
                    const float S_ = sn[pos * 32 + jq + j];
                    nl[j] = lo[j] * C_ - hi[j] * S_;
                    nh[j] = lo[j] * S_ + hi[j] * C_;
                }
                *(uint4*)(row + jq)      = f8h(nl);
                *(uint4*)(row + 32 + jq) = f8h(nh);
            }
        }
    }
    __syncthreads();

    // ---- attention: 1 warp per (window, head) ----
    {
        const int wi = wid & 7, head = wid >> 3;
        const int r16 = lane & 15, hc = (lane >> 4) * 8;
        const uint32_t base = sb + ((uint32_t)((wi * 16 + r16) * TSTRIDE + head * 64 + hc) << 1);
        const uint32_t qb = base + OFF_Q;
        const uint32_t kb = base + OFF_K;
        const uint32_t vb = base + OFF_V;

        float sc[2][4] = {};
        #pragma unroll
        for (int ks = 0; ks < 4; ks++) {
            uint32_t aq[4], bk[4];
            ldsm_x4(aq, qb + ks * 32);
            ldsm_x4(bk, kb + ks * 32);
            mma_f16_16x8x16(sc[0], aq[0], aq[1], aq[2], aq[3], bk[0], bk[2]);
            mma_f16_16x8x16(sc[1], aq[0], aq[1], aq[2], aq[3], bk[1], bk[3]);
        }
        #pragma unroll
        for (int t2 = 0; t2 < 2; t2++)
            #pragma unroll
            for (int q = 0; q < 4; q++)
                sc[t2][q] *= 0.125f;

        float mA = fmaxf(fmaxf(sc[0][0], sc[0][1]), fmaxf(sc[1][0], sc[1][1]));
        float mB = fmaxf(fmaxf(sc[0][2], sc[0][3]), fmaxf(sc[1][2], sc[1][3]));
        mA = fmaxf(mA, __shfl_xor_sync(0xffffffffu, mA, 1));
        mA = fmaxf(mA, __shfl_xor_sync(0xffffffffu, mA, 2));
        mB = fmaxf(mB, __shfl_xor_sync(0xffffffffu, mB, 1));
        mB = fmaxf(mB, __shfl_xor_sync(0xffffffffu, mB, 2));
        float eA0 = expf(sc[0][0] - mA), eA1 = expf(sc[0][1] - mA);
        float eA2 = expf(sc[1][0] - mA), eA3 = expf(sc[1][1] - mA);
        float eB0 = expf(sc[0][2] - mB), eB1 = expf(sc[0][3] - mB);
        float eB2 = expf(sc[1][2] - mB), eB3 = expf(sc[1][3] - mB);
        float sA = eA0 + eA1 + eA2 + eA3;
        float sB = eB0 + eB1 + eB2 + eB3;
        sA += __shfl_xor_sync(0xffffffffu, sA, 1);
        sA += __shfl_xor_sync(0xffffffffu, sA, 2);
        sB += __shfl_xor_sync(0xffffffffu, sB, 1);
        sB += __shfl_xor_sync(0xffffffffu, sB, 2);
        const float iA = 1.f / sA, iB = 1.f / sB;

        const uint32_t p0 = h2u(__floats2half2_rn(eA0 * iA, eA1 * iA));
        const uint32_t p1 = h2u(__floats2half2_rn(eB0 * iB, eB1 * iB));
        const uint32_t p2 = h2u(__floats2half2_rn(eA2 * iA, eA3 * iA));
        const uint32_t p3 = h2u(__floats2half2_rn(eB2 * iB, eB3 * iB));

        float o[8][4] = {};
        #pragma unroll
        for (int nt = 0; nt < 4; nt++) {
            uint32_t bv[4];
            ldsm_x4_trans(bv, vb + nt * 32);
            mma_f16_16x8x16(o[2 * nt],     p0, p1, p2, p3, bv[0], bv[1]);
            mma_f16_16x8x16(o[2 * nt + 1], p0, p1, p2, p3, bv[2], bv[3]);
        }

        const size_t orow = (size_t)(bm + wi * 16 + g);
        const int col0 = bn + head * 64;
        #pragma unroll
        for (int nt = 0; nt < 4; nt++)
            #pragma unroll
            for (int sub = 0; sub < 2; sub++) {
                const int j = 2 * nt + sub;
                const int col = col0 + nt * 16 + sub * 8 + 2 * tid4;
                *(__half2*)(g_attnh + orow * DIM + col) =
                    __floats2half2_rn(o[j][0], o[j][1]);
                *(__half2*)(g_attnh + (orow + 8) * DIM + col) =
                    __floats2half2_rn(o[j][2], o[j][3]);
            }
    }
}

// ---------------------------------------------------------------------------
// WO GEMM: CTA 256x128, BK=64, 512 threads, 16 warps of 64x32. (unchanged)
// ---------------------------------------------------------------------------
constexpr int BM = 256, BN = 128, BK = 64;
constexpr int ROWB   = 144;
constexpr int A_SZ   = BM * ROWB;
constexpr int B_SZ   = BN * ROWB;
constexpr int STG_SZ = A_SZ + B_SZ;
constexpr int GSMEM  = 2 * STG_SZ;          // 110592

__global__ __launch_bounds__(512, 1)
void gemm_wo(float* __restrict__ Cout)
{
    extern __shared__ uint32_t sm[];
    const uint32_t sbu = smem_u32(sm);
    const __half* A = g_attnh;
    const __half* B = g_woh;

    const int tid  = threadIdx.x;
    const int lane = tid & 31, wid = tid >> 5;
    const int g = lane >> 2, tid4 = lane & 3;
    const int warpM = wid & 3;
    const int warpN = wid >> 2;
    const int bm = blockIdx.y * BM, bn = blockIdx.x * BN;

    const int arow = tid >> 3, acc8 = tid & 7;
    const __half* Ag = A + (size_t)(bm + arow) * DIM + acc8 * 8;
    const __half* Bg = B + (size_t)(bn + arow) * DIM + acc8 * 8;
    const uint32_t sdA = sbu + arow * ROWB + acc8 * 16;
    const uint32_t sdB = sbu + A_SZ + arow * ROWB + acc8 * 16;

    auto stage = [&](int s, int kt) {
        const uint32_t so = s * STG_SZ;
        const size_t ko = (size_t)kt * BK;
        #pragma unroll
        for (int i = 0; i < 4; i++)
            cp_async16(sdA + so + i * 64 * ROWB, Ag + ko + (size_t)(64 * i) * DIM);
        #pragma unroll
        for (int i = 0; i < 2; i++)
            cp_async16(sdB + so + i * 64 * ROWB, Bg + ko + (size_t)(64 * i) * DIM);
    };

    const uint32_t aoff = (warpM * 64 + (lane & 15)) * ROWB + ((lane >> 4) << 4);
    const uint32_t boff = A_SZ + (warpN * 32 + (lane & 15)) * ROWB + ((lane >> 4) << 4);

    float acc[4][4][4];
    #pragma unroll
    for (int i = 0; i < 4; i++)
        #pragma unroll
        for (int j = 0; j < 4; j++)
            #pragma unroll
            for (int q = 0; q < 4; q++)
                acc[i][j][q] = 0.f;

    stage(0, 0); cp_commit();

    const int NKT = DIM / BK;
    int s = 0;
    for (int kt = 0; kt < NKT; kt++) {
        cp_wait<0>();
        __syncthreads();
        if (kt + 1 < NKT) { stage(s ^ 1, kt + 1); cp_commit(); }

        const uint32_t ab = sbu + s * STG_SZ + aoff;
        const uint32_t bb = sbu + s * STG_SZ + boff;
        #pragma unroll
        for (int ks = 0; ks < 4; ks++) {
            uint32_t af[4][4], bf[2][4];
            #pragma unroll
            for (int mt = 0; mt < 4; mt++)
                ldsm_x4(af[mt], ab + mt * 16 * ROWB + ks * 32);
            #pragma unroll
            for (int p = 0; p < 2; p++)
                ldsm_x4(bf[p], bb + p * 16 * ROWB + ks * 32);
            #pragma unroll
            for (int mt = 0; mt < 4; mt++)
                #pragma unroll
                for (int p = 0; p < 2; p++) {
                    mma_f16_16x8x16(acc[mt][2 * p],
                                    af[mt][0], af[mt][1], af[mt][2], af[mt][3],
                                    bf[p][0], bf[p][2]);
                    mma_f16_16x8x16(acc[mt][2 * p + 1],
                                    af[mt][0], af[mt][1], af[mt][2], af[mt][3],
                                    bf[p][1], bf[p][3]);
                }
        }
        s ^= 1;
    }

    #pragma unroll
    for (int mt = 0; mt < 4; mt++) {
        const int r0 = bm + warpM * 64 + mt * 16 + g;
        #pragma unroll
        for (int j = 0; j < 4; j++) {
            const int ncol = bn + warpN * 32 + (j >> 1) * 16 + (j & 1) * 8;
            const float* a = acc[mt][j];
            *(float2*)(Cout + (size_t)r0 * DIM + ncol + 2 * tid4) =
                make_float2(a[0], a[1]);
            *(float2*)(Cout + (size_t)(r0 + 8) * DIM + ncol + 2 * tid4) =
                make_float2(a[2], a[3]);
        }
    }
}

// ---------------------------------------------------------------------------
// fp32 -> fp16 prepass: z 0..3 = quarters of x, z 4..7 = weights
// ---------------------------------------------------------------------------
__global__ void prep(const float4* __restrict__ x,
                     const float4* __restrict__ w0, const float4* __restrict__ w1,
                     const float4* __restrict__ w2, const float4* __restrict__ w3)
{
    const int z = blockIdx.z;
    const float4* src;
    uint2* dst;
    int n4;
    if (z < 4) {
        const int quarter = NTOK * DIM / 16;
        src = x + (size_t)z * quarter;
        dst = (uint2*)g_xh + (size_t)z * quarter;
        n4 = quarter;
    } else {
        src = (z == 4) ? w0 : (z == 5) ? w1 : (z == 6) ? w2 : w3;
        dst = (uint2*)((z == 4) ? g_wqh : (z == 5) ? g_wkh : (z == 6) ? g_wvh : g_woh);
        n4 = DIM * DIM / 4;
    }
    int i = blockIdx.x * blockDim.x + threadIdx.x;
    const int stride = gridDim.x * blockDim.x;
    for (; i < n4; i += stride) {
        float4 v = src[i];
        __half2 lo = __floats2half2_rn(v.x, v.y);
        __half2 hi = __floats2half2_rn(v.z, v.w);
        dst[i] = make_uint2(*(uint32_t*)&lo, *(uint32_t*)&hi);
    }
}

// ---------------------------------------------------------------------------
extern "C" void kernel_launch(void* const* d_in, const int* in_sizes, int n_in,
                              void* d_out, int out_size)
{
    const float* x    = (const float*)d_in[0];
    const float* rope = (const float*)d_in[1];
    const float* wq   = (const float*)d_in[2];
    const float* wk   = (const float*)d_in[3];
    const float* wv   = (const float*)d_in[4];
    const float* wo   = (const float*)d_in[5];
    float* out        = (float*)d_out;

    cudaFuncSetAttribute(fused_qkv_attn, cudaFuncAttributeMaxDynamicSharedMemorySize, FSMEM);
    cudaFuncSetAttribute(gemm_wo,        cudaFuncAttributeMaxDynamicSharedMemorySize, GSMEM);

    prep<<<dim3(256, 1, 8), 256>>>((const float4*)x, (const float4*)wq,
                                   (const float4*)wk, (const float4*)wv,
                                   (const float4*)wo);

    fused_qkv_attn<<<dim3(DIM / FBN, NTOK / FBM), 512, FSMEM>>>(rope);

    gemm_wo<<<dim3(DIM / BN, NTOK / BM), 512, GSMEM>>>(out);
}

// round 15
// speedup vs baseline: 1.1882x; 1.0351x over previous
#include <cuda_runtime.h>
#include <cuda_fp16.h>
#include <cstdint>
#include <math.h>

#define DIM    1024
#define HEADS  16
#define HD     64
#define WIN    16
#define NTOK   16384   // B*S
#define NWIN   1024

// Scratch (allocation-free rule: __device__ globals)
__device__ __align__(16) __half g_attnh[NTOK * DIM];
__device__ __align__(16) __half g_xh[NTOK * DIM];
__device__ __align__(16) __half g_wqh[DIM * DIM];
__device__ __align__(16) __half g_wkh[DIM * DIM];
__device__ __align__(16) __half g_wvh[DIM * DIM];
__device__ __align__(16) __half g_woh[DIM * DIM];

// ---------------------------------------------------------------------------
// helpers
// ---------------------------------------------------------------------------
__device__ __forceinline__ uint32_t smem_u32(const void* p) {
    uint32_t a;
    asm("{ .reg .u64 t; cvta.to.shared.u64 t, %1; cvt.u32.u64 %0, t; }"
        : "=r"(a) : "l"(p));
    return a;
}
__device__ __forceinline__ void cp_async16(uint32_t dst, const void* src) {
    asm volatile("cp.async.cg.shared.global [%0], [%1], 16;"
                 :: "r"(dst), "l"(src) : "memory");
}
__device__ __forceinline__ void cp_commit() {
    asm volatile("cp.async.commit_group;" ::: "memory");
}
template <int N>
__device__ __forceinline__ void cp_wait() {
    asm volatile("cp.async.wait_group %0;" :: "n"(N) : "memory");
}
__device__ __forceinline__ void ldsm_x4(uint32_t r[4], uint32_t addr) {
    asm volatile("ldmatrix.sync.aligned.m8n8.x4.shared.b16 {%0,%1,%2,%3}, [%4];"
                 : "=r"(r[0]), "=r"(r[1]), "=r"(r[2]), "=r"(r[3]) : "r"(addr));
}
__device__ __forceinline__ void ldsm_x4_trans(uint32_t r[4], uint32_t addr) {
    asm volatile("ldmatrix.sync.aligned.m8n8.x4.trans.shared.b16 {%0,%1,%2,%3}, [%4];"
                 : "=r"(r[0]), "=r"(r[1]), "=r"(r[2]), "=r"(r[3]) : "r"(addr));
}
__device__ __forceinline__ void mma_f16_16x8x16(float c[4],
                                                uint32_t a0, uint32_t a1,
                                                uint32_t a2, uint32_t a3,
                                                uint32_t b0, uint32_t b1) {
    asm volatile(
        "mma.sync.aligned.m16n8k16.row.col.f32.f16.f16.f32 "
        "{%0,%1,%2,%3}, {%4,%5,%6,%7}, {%8,%9}, {%0,%1,%2,%3};"
        : "+f"(c[0]), "+f"(c[1]), "+f"(c[2]), "+f"(c[3])
        : "r"(a0), "r"(a1), "r"(a2), "r"(a3), "r"(b0), "r"(b1));
}
__device__ __forceinline__ void h8f(const uint4 u, float f[8]) {
    float2 a = __half22float2(*(const __half2*)&u.x);
    float2 b = __half22float2(*(const __half2*)&u.y);
    float2 c = __half22float2(*(const __half2*)&u.z);
    float2 d = __half22float2(*(const __half2*)&u.w);
    f[0]=a.x; f[1]=a.y; f[2]=b.x; f[3]=b.y; f[4]=c.x; f[5]=c.y; f[6]=d.x; f[7]=d.y;
}
__device__ __forceinline__ uint4 f8h(const float f[8]) {
    __half2 a = __floats2half2_rn(f[0], f[1]);
    __half2 b = __floats2half2_rn(f[2], f[3]);
    __half2 c = __floats2half2_rn(f[4], f[5]);
    __half2 d = __floats2half2_rn(f[6], f[7]);
    return make_uint4(*(uint32_t*)&a, *(uint32_t*)&b, *(uint32_t*)&c, *(uint32_t*)&d);
}
__device__ __forceinline__ uint32_t h2u(__half2 h) { return *(uint32_t*)&h; }

// ---------------------------------------------------------------------------
// Fused QKV GEMM + RoPE + windowed attention (R14, unchanged).
// SW128 XOR-swizzled staging: chunk' = chunk ^ (row & 7).
// ---------------------------------------------------------------------------
constexpr int FBM = 128, FBN = 128, FBK = 64;
constexpr int FROWB  = 128;
constexpr int FA_SZ  = FBM * FROWB;             // 16384
constexpr int FB_SZ  = FBN * FROWB;             // 16384
constexpr int FSTG   = FA_SZ + FB_SZ;           // 32768
constexpr int TSTRIDE = 136;
constexpr int TILE_SZ = FBM * TSTRIDE * 2;      // 34816
constexpr int OFF_Q  = 2 * FSTG;                // 65536
constexpr int OFF_K  = OFF_Q + TILE_SZ;         // 100352
constexpr int OFF_V  = OFF_K + TILE_SZ;         // 135168
constexpr int OFF_CS = OFF_V + TILE_SZ;         // 169984
constexpr int OFF_SN = OFF_CS + 2048;
constexpr int FSMEM  = OFF_SN + 2048;           // 174080

__global__ __launch_bounds__(512, 1)
void fused_qkv_attn(const float* __restrict__ rope)
{
    extern __shared__ char smc[];
    const uint32_t sb = smem_u32(smc);
    float* cs = (float*)(smc + OFF_CS);
    float* sn = (float*)(smc + OFF_SN);

    const int tid  = threadIdx.x;
    const int lane = tid & 31, wid = tid >> 5;
    const int g = lane >> 2, tid4 = lane & 3;
    const int warpM = wid & 3, warpN = wid >> 2;
    const int bm = blockIdx.y * FBM, bn = blockIdx.x * FBN;

    sincosf(rope[tid], &sn[tid], &cs[tid]);

    const int srow = tid >> 3, acc8 = tid & 7;
    const int swc  = acc8 ^ (srow & 7);
    const __half* Ag = g_xh + (size_t)(bm + srow) * DIM + acc8 * 8;
    const uint32_t sdA = sb + srow * FROWB + swc * 16;
    const uint32_t sdB = sb + FA_SZ + srow * FROWB + swc * 16;

    auto stage = [&](int s, int kt, const __half* Bw) {
        const uint32_t so = s * FSTG;
        const size_t ko = (size_t)kt * FBK;
        cp_async16(sdA + so,              Ag + ko);
        cp_async16(sdA + so + 64 * FROWB, Ag + ko + (size_t)64 * DIM);
        const __half* Bg = Bw + (size_t)(bn + srow) * DIM + acc8 * 8;
        cp_async16(sdB + so,              Bg + ko);
        cp_async16(sdB + so + 64 * FROWB, Bg + ko + (size_t)64 * DIM);
        cp_commit();
    };

    const int xrow = lane & 7;
    const int hc8  = lane >> 4;
    const uint32_t arow = sb + (uint32_t)(warpM * 32 + (lane & 15)) * FROWB;
    const uint32_t brow = sb + FA_SZ + (uint32_t)(warpN * 32 + (lane & 15)) * FROWB;

    #pragma unroll 1
    for (int ph = 0; ph < 3; ph++) {
        const __half* Bw = (ph == 0) ? g_wqh : (ph == 1) ? g_wkh : g_wvh;

        float acc[2][4][4];
        #pragma unroll
        for (int i = 0; i < 2; i++)
            #pragma unroll
            for (int j = 0; j < 4; j++)
                #pragma unroll
                for (int q = 0; q < 4; q++)
                    acc[i][j][q] = 0.f;

        stage(0, 0, Bw);
        int s = 0;
        #pragma unroll 1
        for (int kt = 0; kt < DIM / FBK; kt++) {
            cp_wait<0>();
            __syncthreads();
            if (kt + 1 < DIM / FBK) stage(s ^ 1, kt + 1, Bw);

            const uint32_t so = s * FSTG;
            #pragma unroll
            for (int ks = 0; ks < 4; ks++) {
                const uint32_t ac = (uint32_t)(((ks * 2 + hc8) ^ xrow) << 4);
                uint32_t af[2][4], bf[2][4];
                ldsm_x4(af[0], arow + so + ac);
                ldsm_x4(af[1], arow + so + 16 * FROWB + ac);
                ldsm_x4(bf[0], brow + so + ac);
                ldsm_x4(bf[1], brow + so + 16 * FROWB + ac);
                #pragma unroll
                for (int mt = 0; mt < 2; mt++)
                    #pragma unroll
                    for (int p = 0; p < 2; p++) {
                        mma_f16_16x8x16(acc[mt][2 * p],
                                        af[mt][0], af[mt][1], af[mt][2], af[mt][3],
                                        bf[p][0], bf[p][2]);
                        mma_f16_16x8x16(acc[mt][2 * p + 1],
                                        af[mt][0], af[mt][1], af[mt][2], af[mt][3],
                                        bf[p][1], bf[p][3]);
                    }
            }
            s ^= 1;
        }

        __half* tp = (__half*)(smc + OFF_Q + ph * TILE_SZ);
        #pragma unroll
        for (int mt = 0; mt < 2; mt++) {
            const int r0 = warpM * 32 + mt * 16 + g;
            #pragma unroll
            for (int j = 0; j < 4; j++) {
                const int ncol = warpN * 32 + (j >> 1) * 16 + (j & 1) * 8 + 2 * tid4;
                *(__half2*)(tp + r0 * TSTRIDE + ncol) =
                    __floats2half2_rn(acc[mt][j][0], acc[mt][j][1]);
                *(__half2*)(tp + (r0 + 8) * TSTRIDE + ncol) =
                    __floats2half2_rn(acc[mt][j][2], acc[mt][j][3]);
            }
        }
    }
    __syncthreads();

    // ---- RoPE in-place on q and k tiles ----
    {
        const int t  = tid >> 2;
        const int jq = (tid & 3) * 8;
        const int pos = t & 15;
        #pragma unroll
        for (int tl = 0; tl < 2; tl++) {
            __half* tb = (__half*)(smc + (tl ? OFF_K : OFF_Q));
            #pragma unroll
            for (int h = 0; h < 2; h++) {
                __half* row = tb + t * TSTRIDE + h * 64;
                float lo[8], hi[8], nl[8], nh[8];
                h8f(*(uint4*)(row + jq), lo);
                h8f(*(uint4*)(row + 32 + jq), hi);
                #pragma unroll
                for (int j = 0; j < 8; j++) {
                    const float C_ = cs[pos * 32 + jq + j];
                    const float S_ = sn[pos * 32 + jq + j];
                    nl[j] = lo[j] * C_ - hi[j] * S_;
                    nh[j] = lo[j] * S_ + hi[j] * C_;
                }
                *(uint4*)(row + jq)      = f8h(nl);
                *(uint4*)(row + 32 + jq) = f8h(nh);
            }
        }
    }
    __syncthreads();

    // ---- attention: 1 warp per (window, head) ----
    {
        const int wi = wid & 7, head = wid >> 3;
        const int r16 = lane & 15, hc = (lane >> 4) * 8;
        const uint32_t base = sb + ((uint32_t)((wi * 16 + r16) * TSTRIDE + head * 64 + hc) << 1);
        const uint32_t qb = base + OFF_Q;
        const uint32_t kb = base + OFF_K;
        const uint32_t vb = base + OFF_V;

        float sc[2][4] = {};
        #pragma unroll
        for (int ks = 0; ks < 4; ks++) {
            uint32_t aq[4], bk[4];
            ldsm_x4(aq, qb + ks * 32);
            ldsm_x4(bk, kb + ks * 32);
            mma_f16_16x8x16(sc[0], aq[0], aq[1], aq[2], aq[3], bk[0], bk[2]);
            mma_f16_16x8x16(sc[1], aq[0], aq[1], aq[2], aq[3], bk[1], bk[3]);
        }
        #pragma unroll
        for (int t2 = 0; t2 < 2; t2++)
            #pragma unroll
            for (int q = 0; q < 4; q++)
                sc[t2][q] *= 0.125f;

        float mA = fmaxf(fmaxf(sc[0][0], sc[0][1]), fmaxf(sc[1][0], sc[1][1]));
        float mB = fmaxf(fmaxf(sc[0][2], sc[0][3]), fmaxf(sc[1][2], sc[1][3]));
        mA = fmaxf(mA, __shfl_xor_sync(0xffffffffu, mA, 1));
        mA = fmaxf(mA, __shfl_xor_sync(0xffffffffu, mA, 2));
        mB = fmaxf(mB, __shfl_xor_sync(0xffffffffu, mB, 1));
        mB = fmaxf(mB, __shfl_xor_sync(0xffffffffu, mB, 2));
        float eA0 = expf(sc[0][0] - mA), eA1 = expf(sc[0][1] - mA);
        float eA2 = expf(sc[1][0] - mA), eA3 = expf(sc[1][1] - mA);
        float eB0 = expf(sc[0][2] - mB), eB1 = expf(sc[0][3] - mB);
        float eB2 = expf(sc[1][2] - mB), eB3 = expf(sc[1][3] - mB);
        float sA = eA0 + eA1 + eA2 + eA3;
        float sB = eB0 + eB1 + eB2 + eB3;
        sA += __shfl_xor_sync(0xffffffffu, sA, 1);
        sA += __shfl_xor_sync(0xffffffffu, sA, 2);
        sB += __shfl_xor_sync(0xffffffffu, sB, 1);
        sB += __shfl_xor_sync(0xffffffffu, sB, 2);
        const float iA = 1.f / sA, iB = 1.f / sB;

        const uint32_t p0 = h2u(__floats2half2_rn(eA0 * iA, eA1 * iA));
        const uint32_t p1 = h2u(__floats2half2_rn(eB0 * iB, eB1 * iB));
        const uint32_t p2 = h2u(__floats2half2_rn(eA2 * iA, eA3 * iA));
        const uint32_t p3 = h2u(__floats2half2_rn(eB2 * iB, eB3 * iB));

        float o[8][4] = {};
        #pragma unroll
        for (int nt = 0; nt < 4; nt++) {
            uint32_t bv[4];
            ldsm_x4_trans(bv, vb + nt * 32);
            mma_f16_16x8x16(o[2 * nt],     p0, p1, p2, p3, bv[0], bv[1]);
            mma_f16_16x8x16(o[2 * nt + 1], p0, p1, p2, p3, bv[2], bv[3]);
        }

        const size_t orow = (size_t)(bm + wi * 16 + g);
        const int col0 = bn + head * 64;
        #pragma unroll
        for (int nt = 0; nt < 4; nt++)
            #pragma unroll
            for (int sub = 0; sub < 2; sub++) {
                const int j = 2 * nt + sub;
                const int col = col0 + nt * 16 + sub * 8 + 2 * tid4;
                *(__half2*)(g_attnh + orow * DIM + col) =
                    __floats2half2_rn(o[j][0], o[j][1]);
                *(__half2*)(g_attnh + (orow + 8) * DIM + col) =
                    __floats2half2_rn(o[j][2], o[j][3]);
            }
    }
}

// ---------------------------------------------------------------------------
// WO GEMM: CTA 256x128, BK=64, 512 threads, 16 warps of 64x32.
// NOW with SW128 XOR-swizzled staging (conflict-free LDSM + STS).
// ---------------------------------------------------------------------------
constexpr int BM = 256, BN = 128, BK = 64;
constexpr int ROWB   = 128;                 // exact rows, swizzled
constexpr int A_SZ   = BM * ROWB;           // 32768
constexpr int B_SZ   = BN * ROWB;           // 16384
constexpr int STG_SZ = A_SZ + B_SZ;         // 49152
constexpr int GSMEM  = 2 * STG_SZ;          // 98304

__global__ __launch_bounds__(512, 1)
void gemm_wo(float* __restrict__ Cout)
{
    extern __shared__ uint32_t sm[];
    const uint32_t sbu = smem_u32(sm);
    const __half* A = g_attnh;
    const __half* B = g_woh;

    const int tid  = threadIdx.x;
    const int lane = tid & 31, wid = tid >> 5;
    const int g = lane >> 2, tid4 = lane & 3;
    const int warpM = wid & 3;
    const int warpN = wid >> 2;
    const int bm = blockIdx.y * BM, bn = blockIdx.x * BN;

    // staging: rows arow + 64*i; chunk acc8, XOR swizzle (row&7 invariant)
    const int arow = tid >> 3, acc8 = tid & 7;
    const int swc  = acc8 ^ (arow & 7);
    const __half* Ag = A + (size_t)(bm + arow) * DIM + acc8 * 8;
    const __half* Bg = B + (size_t)(bn + arow) * DIM + acc8 * 8;
    const uint32_t sdA = sbu + arow * ROWB + swc * 16;
    const uint32_t sdB = sbu + A_SZ + arow * ROWB + swc * 16;

    auto stage = [&](int s, int kt) {
        const uint32_t so = s * STG_SZ;
        const size_t ko = (size_t)kt * BK;
        #pragma unroll
        for (int i = 0; i < 4; i++)
            cp_async16(sdA + so + i * 64 * ROWB, Ag + ko + (size_t)(64 * i) * DIM);
        #pragma unroll
        for (int i = 0; i < 2; i++)
            cp_async16(sdB + so + i * 64 * ROWB, Bg + ko + (size_t)(64 * i) * DIM);
    };

    const int xrow = lane & 7;
    const int hc8  = lane >> 4;
    const uint32_t arow0 = sbu + (uint32_t)(warpM * 64 + (lane & 15)) * ROWB;
    const uint32_t brow0 = sbu + A_SZ + (uint32_t)(warpN * 32 + (lane & 15)) * ROWB;

    float acc[4][4][4];
    #pragma unroll
    for (int i = 0; i < 4; i++)
        #pragma unroll
        for (int j = 0; j < 4; j++)
            #pragma unroll
            for (int q = 0; q < 4; q++)
                acc[i][j][q] = 0.f;

    stage(0, 0); cp_commit();

    const int NKT = DIM / BK;
    int s = 0;
    for (int kt = 0; kt < NKT; kt++) {
        cp_wait<0>();
        __syncthreads();
        if (kt + 1 < NKT) { stage(s ^ 1, kt + 1); cp_commit(); }

        const uint32_t so = s * STG_SZ;
        #pragma unroll
        for (int ks = 0; ks < 4; ks++) {
            const uint32_t ac = (uint32_t)(((ks * 2 + hc8) ^ xrow) << 4);
            uint32_t af[4][4], bf[2][4];
            #pragma unroll
            for (int mt = 0; mt < 4; mt++)
                ldsm_x4(af[mt], arow0 + so + mt * 16 * ROWB + ac);
            #pragma unroll
            for (int p = 0; p < 2; p++)
                ldsm_x4(bf[p], brow0 + so + p * 16 * ROWB + ac);
            #pragma unroll
            for (int mt = 0; mt < 4; mt++)
                #pragma unroll
                for (int p = 0; p < 2; p++) {
                    mma_f16_16x8x16(acc[mt][2 * p],
                                    af[mt][0], af[mt][1], af[mt][2], af[mt][3],
                                    bf[p][0], bf[p][2]);
                    mma_f16_16x8x16(acc[mt][2 * p + 1],
                                    af[mt][0], af[mt][1], af[mt][2], af[mt][3],
                                    bf[p][1], bf[p][3]);
                }
        }
        s ^= 1;
    }

    #pragma unroll
    for (int mt = 0; mt < 4; mt++) {
        const int r0 = bm + warpM * 64 + mt * 16 + g;
        #pragma unroll
        for (int j = 0; j < 4; j++) {
            const int ncol = bn + warpN * 32 + (j >> 1) * 16 + (j & 1) * 8;
            const float* a = acc[mt][j];
            *(float2*)(Cout + (size_t)r0 * DIM + ncol + 2 * tid4) =
                make_float2(a[0], a[1]);
            *(float2*)(Cout + (size_t)(r0 + 8) * DIM + ncol + 2 * tid4) =
                make_float2(a[2], a[3]);
        }
    }
}

// ---------------------------------------------------------------------------
// fp32 -> fp16 prepass: z 0..3 = quarters of x, z 4..7 = weights
// ---------------------------------------------------------------------------
__global__ void prep(const float4* __restrict__ x,
                     const float4* __restrict__ w0, const float4* __restrict__ w1,
                     const float4* __restrict__ w2, const float4* __restrict__ w3)
{
    const int z = blockIdx.z;
    const float4* src;
    uint2* dst;
    int n4;
    if (z < 4) {
        const int quarter = NTOK * DIM / 16;
        src = x + (size_t)z * quarter;
        dst = (uint2*)g_xh + (size_t)z * quarter;
        n4 = quarter;
    } else {
        src = (z == 4) ? w0 : (z == 5) ? w1 : (z == 6) ? w2 : w3;
        dst = (uint2*)((z == 4) ? g_wqh : (z == 5) ? g_wkh : (z == 6) ? g_wvh : g_woh);
        n4 = DIM * DIM / 4;
    }
    int i = blockIdx.x * blockDim.x + threadIdx.x;
    const int stride = gridDim.x * blockDim.x;
    for (; i < n4; i += stride) {
        float4 v = src[i];
        __half2 lo = __floats2half2_rn(v.x, v.y);
        __half2 hi = __floats2half2_rn(v.z, v.w);
        dst[i] = make_uint2(*(uint32_t*)&lo, *(uint32_t*)&hi);
    }
}

// ---------------------------------------------------------------------------
extern "C" void kernel_launch(void* const* d_in, const int* in_sizes, int n_in,
                              void* d_out, int out_size)
{
    const float* x    = (const float*)d_in[0];
    const float* rope = (const float*)d_in[1];
    const float* wq   = (const float*)d_in[2];
    const float* wk   = (const float*)d_in[3];
    const float* wv   = (const float*)d_in[4];
    const float* wo   = (const float*)d_in[5];
    float* out        = (float*)d_out;

    cudaFuncSetAttribute(fused_qkv_attn, cudaFuncAttributeMaxDynamicSharedMemorySize, FSMEM);
    cudaFuncSetAttribute(gemm_wo,        cudaFuncAttributeMaxDynamicSharedMemorySize, GSMEM);

    prep<<<dim3(256, 1, 8), 256>>>((const float4*)x, (const float4*)wq,
                                   (const float4*)wk, (const float4*)wv,
                                   (const float4*)wo);

    fused_qkv_attn<<<dim3(DIM / FBN, NTOK / FBM), 512, FSMEM>>>(rope);

    gemm_wo<<<dim3(DIM / BN, NTOK / BM), 512, GSMEM>>>(out);
}

// round 16
// speedup vs baseline: 1.1889x; 1.0006x over previous
#include <cuda_runtime.h>
#include <cuda_fp16.h>
#include <cstdint>
#include <math.h>

#define DIM    1024
#define HEADS  16
#define HD     64
#define WIN    16
#define NTOK   16384   // B*S
#define NWIN   1024

// Scratch (allocation-free rule: __device__ globals)
__device__ __align__(16) __half g_attnh[NTOK * DIM];
__device__ __align__(16) __half g_xh[NTOK * DIM];
__device__ __align__(16) __half g_wqh[DIM * DIM];
__device__ __align__(16) __half g_wkh[DIM * DIM];
__device__ __align__(16) __half g_wvh[DIM * DIM];
__device__ __align__(16) __half g_woh[DIM * DIM];

// ---------------------------------------------------------------------------
// helpers
// ---------------------------------------------------------------------------
__device__ __forceinline__ uint32_t smem_u32(const void* p) {
    uint32_t a;
    asm("{ .reg .u64 t; cvta.to.shared.u64 t, %1; cvt.u32.u64 %0, t; }"
        : "=r"(a) : "l"(p));
    return a;
}
__device__ __forceinline__ void cp_async16(uint32_t dst, const void* src) {
    asm volatile("cp.async.cg.shared.global [%0], [%1], 16;"
                 :: "r"(dst), "l"(src) : "memory");
}
__device__ __forceinline__ void cp_commit() {
    asm volatile("cp.async.commit_group;" ::: "memory");
}
template <int N>
__device__ __forceinline__ void cp_wait() {
    asm volatile("cp.async.wait_group %0;" :: "n"(N) : "memory");
}
__device__ __forceinline__ void ldsm_x4(uint32_t r[4], uint32_t addr) {
    asm volatile("ldmatrix.sync.aligned.m8n8.x4.shared.b16 {%0,%1,%2,%3}, [%4];"
                 : "=r"(r[0]), "=r"(r[1]), "=r"(r[2]), "=r"(r[3]) : "r"(addr));
}
__device__ __forceinline__ void ldsm_x4_trans(uint32_t r[4], uint32_t addr) {
    asm volatile("ldmatrix.sync.aligned.m8n8.x4.trans.shared.b16 {%0,%1,%2,%3}, [%4];"
                 : "=r"(r[0]), "=r"(r[1]), "=r"(r[2]), "=r"(r[3]) : "r"(addr));
}
__device__ __forceinline__ void mma_f16_16x8x16(float c[4],
                                                uint32_t a0, uint32_t a1,
                                                uint32_t a2, uint32_t a3,
                                                uint32_t b0, uint32_t b1) {
    asm volatile(
        "mma.sync.aligned.m16n8k16.row.col.f32.f16.f16.f32 "
        "{%0,%1,%2,%3}, {%4,%5,%6,%7}, {%8,%9}, {%0,%1,%2,%3};"
        : "+f"(c[0]), "+f"(c[1]), "+f"(c[2]), "+f"(c[3])
        : "r"(a0), "r"(a1), "r"(a2), "r"(a3), "r"(b0), "r"(b1));
}
__device__ __forceinline__ uint32_t h2u(__half2 h) { return *(uint32_t*)&h; }

// ---------------------------------------------------------------------------
// Fused QKV GEMM + in-register RoPE + windowed attention.
// SW128 XOR-swizzled staging: chunk' = chunk ^ (row & 7).
// CTA tile 128 tokens x 128 cols (= 8 windows x 2 heads). 512 threads,
// 16 warps of 32x32 GEMM tiles; attention: 1 warp per (window, head).
// RoPE is applied to q/k ldmatrix fragments in registers: pairs (d, d+32)
// live in regs (frag[ks][j], frag[ks+2][j]) of the SAME thread.
// ---------------------------------------------------------------------------
constexpr int FBM = 128, FBN = 128, FBK = 64;
constexpr int FROWB  = 128;
constexpr int FA_SZ  = FBM * FROWB;             // 16384
constexpr int FB_SZ  = FBN * FROWB;             // 16384
constexpr int FSTG   = FA_SZ + FB_SZ;           // 32768
constexpr int TSTRIDE = 136;
constexpr int TILE_SZ = FBM * TSTRIDE * 2;      // 34816
constexpr int OFF_Q  = 2 * FSTG;                // 65536
constexpr int OFF_K  = OFF_Q + TILE_SZ;         // 100352
constexpr int OFF_V  = OFF_K + TILE_SZ;         // 135168
constexpr int OFF_CS = OFF_V + TILE_SZ;         // 169984
constexpr int OFF_SN = OFF_CS + 2048;
constexpr int FSMEM  = OFF_SN + 2048;           // 174080

__global__ __launch_bounds__(512, 1)
void fused_qkv_attn(const float* __restrict__ rope)
{
    extern __shared__ char smc[];
    const uint32_t sb = smem_u32(smc);
    float* cs = (float*)(smc + OFF_CS);
    float* sn = (float*)(smc + OFF_SN);

    const int tid  = threadIdx.x;
    const int lane = tid & 31, wid = tid >> 5;
    const int g = lane >> 2, tid4 = lane & 3;
    const int warpM = wid & 3, warpN = wid >> 2;
    const int bm = blockIdx.y * FBM, bn = blockIdx.x * FBN;

    sincosf(rope[tid], &sn[tid], &cs[tid]);   // [pos][freq] = [16][32]

    const int srow = tid >> 3, acc8 = tid & 7;
    const int swc  = acc8 ^ (srow & 7);
    const __half* Ag = g_xh + (size_t)(bm + srow) * DIM + acc8 * 8;
    const uint32_t sdA = sb + srow * FROWB + swc * 16;
    const uint32_t sdB = sb + FA_SZ + srow * FROWB + swc * 16;

    auto stage = [&](int s, int kt, const __half* Bw) {
        const uint32_t so = s * FSTG;
        const size_t ko = (size_t)kt * FBK;
        cp_async16(sdA + so,              Ag + ko);
        cp_async16(sdA + so + 64 * FROWB, Ag + ko + (size_t)64 * DIM);
        const __half* Bg = Bw + (size_t)(bn + srow) * DIM + acc8 * 8;
        cp_async16(sdB + so,              Bg + ko);
        cp_async16(sdB + so + 64 * FROWB, Bg + ko + (size_t)64 * DIM);
        cp_commit();
    };

    const int xrow = lane & 7;
    const int hc8  = lane >> 4;
    const uint32_t arow = sb + (uint32_t)(warpM * 32 + (lane & 15)) * FROWB;
    const uint32_t brow = sb + FA_SZ + (uint32_t)(warpN * 32 + (lane & 15)) * FROWB;

    // ---- 3 GEMM phases: q, k, v ----
    #pragma unroll 1
    for (int ph = 0; ph < 3; ph++) {
        const __half* Bw = (ph == 0) ? g_wqh : (ph == 1) ? g_wkh : g_wvh;

        float acc[2][4][4];
        #pragma unroll
        for (int i = 0; i < 2; i++)
            #pragma unroll
            for (int j = 0; j < 4; j++)
                #pragma unroll
                for (int q = 0; q < 4; q++)
                    acc[i][j][q] = 0.f;

        stage(0, 0, Bw);
        int s = 0;
        #pragma unroll 1
        for (int kt = 0; kt < DIM / FBK; kt++) {
            cp_wait<0>();
            __syncthreads();
            if (kt + 1 < DIM / FBK) stage(s ^ 1, kt + 1, Bw);

            const uint32_t so = s * FSTG;
            #pragma unroll
            for (int ks = 0; ks < 4; ks++) {
                const uint32_t ac = (uint32_t)(((ks * 2 + hc8) ^ xrow) << 4);
                uint32_t af[2][4], bf[2][4];
                ldsm_x4(af[0], arow + so + ac);
                ldsm_x4(af[1], arow + so + 16 * FROWB + ac);
                ldsm_x4(bf[0], brow + so + ac);
                ldsm_x4(bf[1], brow + so + 16 * FROWB + ac);
                #pragma unroll
                for (int mt = 0; mt < 2; mt++)
                    #pragma unroll
                    for (int p = 0; p < 2; p++) {
                        mma_f16_16x8x16(acc[mt][2 * p],
                                        af[mt][0], af[mt][1], af[mt][2], af[mt][3],
                                        bf[p][0], bf[p][2]);
                        mma_f16_16x8x16(acc[mt][2 * p + 1],
                                        af[mt][0], af[mt][1], af[mt][2], af[mt][3],
                                        bf[p][1], bf[p][3]);
                    }
            }
            s ^= 1;
        }

        __half* tp = (__half*)(smc + OFF_Q + ph * TILE_SZ);
        #pragma unroll
        for (int mt = 0; mt < 2; mt++) {
            const int r0 = warpM * 32 + mt * 16 + g;
            #pragma unroll
            for (int j = 0; j < 4; j++) {
                const int ncol = warpN * 32 + (j >> 1) * 16 + (j & 1) * 8 + 2 * tid4;
                *(__half2*)(tp + r0 * TSTRIDE + ncol) =
                    __floats2half2_rn(acc[mt][j][0], acc[mt][j][1]);
                *(__half2*)(tp + (r0 + 8) * TSTRIDE + ncol) =
                    __floats2half2_rn(acc[mt][j][2], acc[mt][j][3]);
            }
        }
    }
    __syncthreads();

    // ---- attention: 1 warp per (window, head), RoPE in registers ----
    {
        const int wi = wid & 7, head = wid >> 3;
        const int r16 = lane & 15, hc = (lane >> 4) * 8;
        const uint32_t base = sb + ((uint32_t)((wi * 16 + r16) * TSTRIDE + head * 64 + hc) << 1);
        const uint32_t qb = base + OFF_Q;
        const uint32_t kb = base + OFF_K;
        const uint32_t vb = base + OFF_V;

        // load all 4 k16 fragments of q and k
        uint32_t aq[4][4], bk[4][4];
        #pragma unroll
        for (int ks = 0; ks < 4; ks++) {
            ldsm_x4(aq[ks], qb + ks * 32);
            ldsm_x4(bk[ks], kb + ks * 32);
        }

        // in-register RoPE: element (lane, reg j, half h) of fragment ks has
        //   token pos = g + (j&1)*8,  d = ks*16 + (j>=2)*8 + 2*tid4 + h
        // rotation pairs (d, d+32) = (frag[ks][j], frag[ks+2][j]), ks in {0,1}
        #pragma unroll
        for (int ks = 0; ks < 2; ks++) {
            #pragma unroll
            for (int j = 0; j < 4; j++) {
                const int pos = g + (j & 1) * 8;
                const int p0  = ks * 16 + ((j >> 1) & 1) * 8 + 2 * tid4;
                const float c0 = cs[pos * 32 + p0],     s0 = sn[pos * 32 + p0];
                const float c1 = cs[pos * 32 + p0 + 1], s1 = sn[pos * 32 + p0 + 1];
                // q
                {
                    float2 x = __half22float2(*(__half2*)&aq[ks][j]);
                    float2 y = __half22float2(*(__half2*)&aq[ks + 2][j]);
                    __half2 nx = __floats2half2_rn(x.x * c0 - y.x * s0,
                                                   x.y * c1 - y.y * s1);
                    __half2 ny = __floats2half2_rn(x.x * s0 + y.x * c0,
                                                   x.y * s1 + y.y * c1);
                    aq[ks][j]     = h2u(nx);
                    aq[ks + 2][j] = h2u(ny);
                }
                // k
                {
                    float2 x = __half22float2(*(__half2*)&bk[ks][j]);
                    float2 y = __half22float2(*(__half2*)&bk[ks + 2][j]);
                    __half2 nx = __floats2half2_rn(x.x * c0 - y.x * s0,
                                                   x.y * c1 - y.y * s1);
                    __half2 ny = __floats2half2_rn(x.x * s0 + y.x * c0,
                                                   x.y * s1 + y.y * c1);
                    bk[ks][j]     = h2u(nx);
                    bk[ks + 2][j] = h2u(ny);
                }
            }
        }

        // scores S = q . k^T  (16x16), fp32 accum
        float sc[2][4] = {};
        #pragma unroll
        for (int ks = 0; ks < 4; ks++) {
            mma_f16_16x8x16(sc[0], aq[ks][0], aq[ks][1], aq[ks][2], aq[ks][3],
                            bk[ks][0], bk[ks][2]);
            mma_f16_16x8x16(sc[1], aq[ks][0], aq[ks][1], aq[ks][2], aq[ks][3],
                            bk[ks][1], bk[ks][3]);
        }
        #pragma unroll
        for (int t2 = 0; t2 < 2; t2++)
            #pragma unroll
            for (int q = 0; q < 4; q++)
                sc[t2][q] *= 0.125f;

        float mA = fmaxf(fmaxf(sc[0][0], sc[0][1]), fmaxf(sc[1][0], sc[1][1]));
        float mB = fmaxf(fmaxf(sc[0][2], sc[0][3]), fmaxf(sc[1][2], sc[1][3]));
        mA = fmaxf(mA, __shfl_xor_sync(0xffffffffu, mA, 1));
        mA = fmaxf(mA, __shfl_xor_sync(0xffffffffu, mA, 2));
        mB = fmaxf(mB, __shfl_xor_sync(0xffffffffu, mB, 1));
        mB = fmaxf(mB, __shfl_xor_sync(0xffffffffu, mB, 2));
        float eA0 = expf(sc[0][0] - mA), eA1 = expf(sc[0][1] - mA);
        float eA2 = expf(sc[1][0] - mA), eA3 = expf(sc[1][1] - mA);
        float eB0 = expf(sc[0][2] - mB), eB1 = expf(sc[0][3] - mB);
        float eB2 = expf(sc[1][2] - mB), eB3 = expf(sc[1][3] - mB);
        float sA = eA0 + eA1 + eA2 + eA3;
        float sB = eB0 + eB1 + eB2 + eB3;
        sA += __shfl_xor_sync(0xffffffffu, sA, 1);
        sA += __shfl_xor_sync(0xffffffffu, sA, 2);
        sB += __shfl_xor_sync(0xffffffffu, sB, 1);
        sB += __shfl_xor_sync(0xffffffffu, sB, 2);
        const float iA = 1.f / sA, iB = 1.f / sB;

        const uint32_t p0 = h2u(__floats2half2_rn(eA0 * iA, eA1 * iA));
        const uint32_t p1 = h2u(__floats2half2_rn(eB0 * iB, eB1 * iB));
        const uint32_t p2 = h2u(__floats2half2_rn(eA2 * iA, eA3 * iA));
        const uint32_t p3 = h2u(__floats2half2_rn(eB2 * iB, eB3 * iB));

        float o[8][4] = {};
        #pragma unroll
        for (int nt = 0; nt < 4; nt++) {
            uint32_t bv[4];
            ldsm_x4_trans(bv, vb + nt * 32);
            mma_f16_16x8x16(o[2 * nt],     p0, p1, p2, p3, bv[0], bv[1]);
            mma_f16_16x8x16(o[2 * nt + 1], p0, p1, p2, p3, bv[2], bv[3]);
        }

        const size_t orow = (size_t)(bm + wi * 16 + g);
        const int col0 = bn + head * 64;
        #pragma unroll
        for (int nt = 0; nt < 4; nt++)
            #pragma unroll
            for (int sub = 0; sub < 2; sub++) {
                const int j = 2 * nt + sub;
                const int col = col0 + nt * 16 + sub * 8 + 2 * tid4;
                *(__half2*)(g_attnh + orow * DIM + col) =
                    __floats2half2_rn(o[j][0], o[j][1]);
                *(__half2*)(g_attnh + (orow + 8) * DIM + col) =
                    __floats2half2_rn(o[j][2], o[j][3]);
            }
    }
}

// ---------------------------------------------------------------------------
// WO GEMM: CTA 256x128, BK=64, 512 threads, 16 warps of 64x32.
// SW128 XOR-swizzled staging (conflict-free LDSM + STS). (unchanged R15)
// ---------------------------------------------------------------------------
constexpr int BM = 256, BN = 128, BK = 64;
constexpr int ROWB   = 128;
constexpr int A_SZ   = BM * ROWB;           // 32768
constexpr int B_SZ   = BN * ROWB;           // 16384
constexpr int STG_SZ = A_SZ + B_SZ;         // 49152
constexpr int GSMEM  = 2 * STG_SZ;          // 98304

__global__ __launch_bounds__(512, 1)
void gemm_wo(float* __restrict__ Cout)
{
    extern __shared__ uint32_t sm[];
    const uint32_t sbu = smem_u32(sm);
    const __half* A = g_attnh;
    const __half* B = g_woh;

    const int tid  = threadIdx.x;
    const int lane = tid & 31, wid = tid >> 5;
    const int g = lane >> 2, tid4 = lane & 3;
    const int warpM = wid & 3;
    const int warpN = wid >> 2;
    const int bm = blockIdx.y * BM, bn = blockIdx.x * BN;

    const int arow = tid >> 3, acc8 = tid & 7;
    const int swc  = acc8 ^ (arow & 7);
    const __half* Ag = A + (size_t)(bm + arow) * DIM + acc8 * 8;
    const __half* Bg = B + (size_t)(bn + arow) * DIM + acc8 * 8;
    const uint32_t sdA = sbu + arow * ROWB + swc * 16;
    const uint32_t sdB = sbu + A_SZ + arow * ROWB + swc * 16;

    auto stage = [&](int s, int kt) {
        const uint32_t so = s * STG_SZ;
        const size_t ko = (size_t)kt * BK;
        #pragma unroll
        for (int i = 0; i < 4; i++)
            cp_async16(sdA + so + i * 64 * ROWB, Ag + ko + (size_t)(64 * i) * DIM);
        #pragma unroll
        for (int i = 0; i < 2; i++)
            cp_async16(sdB + so + i * 64 * ROWB, Bg + ko + (size_t)(64 * i) * DIM);
    };

    const int xrow = lane & 7;
    const int hc8  = lane >> 4;
    const uint32_t arow0 = sbu + (uint32_t)(warpM * 64 + (lane & 15)) * ROWB;
    const uint32_t brow0 = sbu + A_SZ + (uint32_t)(warpN * 32 + (lane & 15)) * ROWB;

    float acc[4][4][4];
    #pragma unroll
    for (int i = 0; i < 4; i++)
        #pragma unroll
        for (int j = 0; j < 4; j++)
            #pragma unroll
            for (int q = 0; q < 4; q++)
                acc[i][j][q] = 0.f;

    stage(0, 0); cp_commit();

    const int NKT = DIM / BK;
    int s = 0;
    for (int kt = 0; kt < NKT; kt++) {
        cp_wait<0>();
        __syncthreads();
        if (kt + 1 < NKT) { stage(s ^ 1, kt + 1); cp_commit(); }

        const uint32_t so = s * STG_SZ;
        #pragma unroll
        for (int ks = 0; ks < 4; ks++) {
            const uint32_t ac = (uint32_t)(((ks * 2 + hc8) ^ xrow) << 4);
            uint32_t af[4][4], bf[2][4];
            #pragma unroll
            for (int mt = 0; mt < 4; mt++)
                ldsm_x4(af[mt], arow0 + so + mt * 16 * ROWB + ac);
            #pragma unroll
            for (int p = 0; p < 2; p++)
                ldsm_x4(bf[p], brow0 + so + p * 16 * ROWB + ac);
            #pragma unroll
            for (int mt = 0; mt < 4; mt++)
                #pragma unroll
                for (int p = 0; p < 2; p++) {
                    mma_f16_16x8x16(acc[mt][2 * p],
                                    af[mt][0], af[mt][1], af[mt][2], af[mt][3],
                                    bf[p][0], bf[p][2]);
                    mma_f16_16x8x16(acc[mt][2 * p + 1],
                                    af[mt][0], af[mt][1], af[mt][2], af[mt][3],
                                    bf[p][1], bf[p][3]);
                }
        }
        s ^= 1;
    }

    #pragma unroll
    for (int mt = 0; mt < 4; mt++) {
        const int r0 = bm + warpM * 64 + mt * 16 + g;
        #pragma unroll
        for (int j = 0; j < 4; j++) {
            const int ncol = bn + warpN * 32 + (j >> 1) * 16 + (j & 1) * 8;
            const float* a = acc[mt][j];
            *(float2*)(Cout + (size_t)r0 * DIM + ncol + 2 * tid4) =
                make_float2(a[0], a[1]);
            *(float2*)(Cout + (size_t)(r0 + 8) * DIM + ncol + 2 * tid4) =
                make_float2(a[2], a[3]);
        }
    }
}

// ---------------------------------------------------------------------------
// fp32 -> fp16 prepass: z 0..3 = quarters of x, z 4..7 = weights
// ---------------------------------------------------------------------------
__global__ void prep(const float4* __restrict__ x,
                     const float4* __restrict__ w0, const float4* __restrict__ w1,
                     const float4* __restrict__ w2, const float4* __restrict__ w3)
{
    const int z = blockIdx.z;
    const float4* src;
    uint2* dst;
    int n4;
    if (z < 4) {
        const int quarter = NTOK * DIM / 16;
        src = x + (size_t)z * quarter;
        dst = (uint2*)g_xh + (size_t)z * quarter;
        n4 = quarter;
    } else {
        src = (z == 4) ? w0 : (z == 5) ? w1 : (z == 6) ? w2 : w3;
        dst = (uint2*)((z == 4) ? g_wqh : (z == 5) ? g_wkh : (z == 6) ? g_wvh : g_woh);
        n4 = DIM * DIM / 4;
    }
    int i = blockIdx.x * blockDim.x + threadIdx.x;
    const int stride = gridDim.x * blockDim.x;
    for (; i < n4; i += stride) {
        float4 v = src[i];
        __half2 lo = __floats2half2_rn(v.x, v.y);
        __half2 hi = __floats2half2_rn(v.z, v.w);
        dst[i] = make_uint2(*(uint32_t*)&lo, *(uint32_t*)&hi);
    }
}

// ---------------------------------------------------------------------------
extern "C" void kernel_launch(void* const* d_in, const int* in_sizes, int n_in,
                              void* d_out, int out_size)
{
    const float* x    = (const float*)d_in[0];
    const float* rope = (const float*)d_in[1];
    const float* wq   = (const float*)d_in[2];
    const float* wk   = (const float*)d_in[3];
    const float* wv   = (const float*)d_in[4];
    const float* wo   = (const float*)d_in[5];
    float* out        = (float*)d_out;

    cudaFuncSetAttribute(fused_qkv_attn, cudaFuncAttributeMaxDynamicSharedMemorySize, FSMEM);
    cudaFuncSetAttribute(gemm_wo,        cudaFuncAttributeMaxDynamicSharedMemorySize, GSMEM);

    prep<<<dim3(256, 1, 8), 256>>>((const float4*)x, (const float4*)wq,
                                   (const float4*)wk, (const float4*)wv,
                                   (const float4*)wo);

    fused_qkv_attn<<<dim3(DIM / FBN, NTOK / FBM), 512, FSMEM>>>(rope);

    gemm_wo<<<dim3(DIM / BN, NTOK / BM), 512, GSMEM>>>(out);
}

// round 17
// speedup vs baseline: 1.2027x; 1.0116x over previous
#include <cuda_runtime.h>
#include <cuda_fp16.h>
#include <cstdint>
#include <math.h>

#define DIM    1024
#define HEADS  16
#define HD     64
#define WIN    16
#define NTOK   16384   // B*S
#define NWIN   1024

// Scratch (allocation-free rule: __device__ globals)
__device__ __align__(16) __half g_attnh[NTOK * DIM];
__device__ __align__(16) __half g_xh[NTOK * DIM];
__device__ __align__(16) __half g_wqh[DIM * DIM];
__device__ __align__(16) __half g_wkh[DIM * DIM];
__device__ __align__(16) __half g_wvh[DIM * DIM];
__device__ __align__(16) __half g_woh[DIM * DIM];

// ---------------------------------------------------------------------------
// helpers
// ---------------------------------------------------------------------------
__device__ __forceinline__ uint32_t smem_u32(const void* p) {
    uint32_t a;
    asm("{ .reg .u64 t; cvta.to.shared.u64 t, %1; cvt.u32.u64 %0, t; }"
        : "=r"(a) : "l"(p));
    return a;
}
__device__ __forceinline__ void cp_async16(uint32_t dst, const void* src) {
    asm volatile("cp.async.cg.shared.global [%0], [%1], 16;"
                 :: "r"(dst), "l"(src) : "memory");
}
__device__ __forceinline__ void cp_commit() {
    asm volatile("cp.async.commit_group;" ::: "memory");
}
template <int N>
__device__ __forceinline__ void cp_wait() {
    asm volatile("cp.async.wait_group %0;" :: "n"(N) : "memory");
}
__device__ __forceinline__ void ldsm_x4(uint32_t r[4], uint32_t addr) {
    asm volatile("ldmatrix.sync.aligned.m8n8.x4.shared.b16 {%0,%1,%2,%3}, [%4];"
                 : "=r"(r[0]), "=r"(r[1]), "=r"(r[2]), "=r"(r[3]) : "r"(addr));
}
__device__ __forceinline__ void ldsm_x4_trans(uint32_t r[4], uint32_t addr) {
    asm volatile("ldmatrix.sync.aligned.m8n8.x4.trans.shared.b16 {%0,%1,%2,%3}, [%4];"
                 : "=r"(r[0]), "=r"(r[1]), "=r"(r[2]), "=r"(r[3]) : "r"(addr));
}
__device__ __forceinline__ void mma_f16_16x8x16(float c[4],
                                                uint32_t a0, uint32_t a1,
                                                uint32_t a2, uint32_t a3,
                                                uint32_t b0, uint32_t b1) {
    asm volatile(
        "mma.sync.aligned.m16n8k16.row.col.f32.f16.f16.f32 "
        "{%0,%1,%2,%3}, {%4,%5,%6,%7}, {%8,%9}, {%0,%1,%2,%3};"
        : "+f"(c[0]), "+f"(c[1]), "+f"(c[2]), "+f"(c[3])
        : "r"(a0), "r"(a1), "r"(a2), "r"(a3), "r"(b0), "r"(b1));
}
__device__ __forceinline__ uint32_t h2u(__half2 h) { return *(uint32_t*)&h; }

// ---------------------------------------------------------------------------
// Fused QKV GEMM + in-register RoPE + windowed attention.
// CTA tile 128 tokens x 64 cols (= 8 windows x 1 head). 256 threads,
// 8 warps of 32x32 GEMM tiles; attention: 1 warp per (window, head).
// SW128 XOR-swizzled staging; ~106KB smem -> 2 CTAs/SM (cross-CTA overlap).
// ---------------------------------------------------------------------------
constexpr int FBM = 128, FBN = 64, FBK = 64;
constexpr int FROWB  = 128;
constexpr int FA_SZ  = FBM * FROWB;             // 16384
constexpr int FB_SZ  = FBN * FROWB;             // 8192
constexpr int FSTG   = FA_SZ + FB_SZ;           // 24576
constexpr int TSTRIDE = 72;                     // tile row stride (halves)
constexpr int TILE_SZ = FBM * TSTRIDE * 2;      // 18432
constexpr int OFF_Q  = 2 * FSTG;                // 49152
constexpr int OFF_K  = OFF_Q + TILE_SZ;         // 67584
constexpr int OFF_V  = OFF_K + TILE_SZ;         // 86016
constexpr int OFF_CS = OFF_V + TILE_SZ;         // 104448
constexpr int OFF_SN = OFF_CS + 2048;           // 106496
constexpr int FSMEM  = OFF_SN + 2048;           // 108544

__global__ __launch_bounds__(256, 2)
void fused_qkv_attn(const float* __restrict__ rope)
{
    extern __shared__ char smc[];
    const uint32_t sb = smem_u32(smc);
    float* cs = (float*)(smc + OFF_CS);
    float* sn = (float*)(smc + OFF_SN);

    const int tid  = threadIdx.x;
    const int lane = tid & 31, wid = tid >> 5;
    const int g = lane >> 2, tid4 = lane & 3;
    const int warpM = wid & 3, warpN = wid >> 2;   // 4 x 2 of 32x32
    const int bm = blockIdx.y * FBM, bn = blockIdx.x * FBN;

    // rope table [16][32]: 2 elems per thread
    sincosf(rope[tid],       &sn[tid],       &cs[tid]);
    sincosf(rope[tid + 256], &sn[tid + 256], &cs[tid + 256]);

    // staging: rows srow + 32*i, chunk acc8 (16B), XOR swizzle
    const int srow = tid >> 3, acc8 = tid & 7;
    const int swc  = acc8 ^ (srow & 7);             // (srow+32i)&7 invariant
    const __half* Ag = g_xh + (size_t)(bm + srow) * DIM + acc8 * 8;
    const uint32_t sdA = sb + srow * FROWB + swc * 16;
    const uint32_t sdB = sb + FA_SZ + srow * FROWB + swc * 16;

    auto stage = [&](int s, int kt, const __half* Bw) {
        const uint32_t so = s * FSTG;
        const size_t ko = (size_t)kt * FBK;
        #pragma unroll
        for (int i = 0; i < 4; i++)
            cp_async16(sdA + so + i * 32 * FROWB, Ag + ko + (size_t)(32 * i) * DIM);
        const __half* Bg = Bw + (size_t)(bn + srow) * DIM + acc8 * 8;
        #pragma unroll
        for (int i = 0; i < 2; i++)
            cp_async16(sdB + so + i * 32 * FROWB, Bg + ko + (size_t)(32 * i) * DIM);
        cp_commit();
    };

    const int xrow = lane & 7;
    const int hc8  = lane >> 4;
    const uint32_t arow = sb + (uint32_t)(warpM * 32 + (lane & 15)) * FROWB;
    const uint32_t brow = sb + FA_SZ + (uint32_t)(warpN * 32 + (lane & 15)) * FROWB;

    // ---- 3 GEMM phases: q, k, v ----
    #pragma unroll 1
    for (int ph = 0; ph < 3; ph++) {
        const __half* Bw = (ph == 0) ? g_wqh : (ph == 1) ? g_wkh : g_wvh;

        float acc[2][4][4];
        #pragma unroll
        for (int i = 0; i < 2; i++)
            #pragma unroll
            for (int j = 0; j < 4; j++)
                #pragma unroll
                for (int q = 0; q < 4; q++)
                    acc[i][j][q] = 0.f;

        stage(0, 0, Bw);
        int s = 0;
        #pragma unroll 1
        for (int kt = 0; kt < DIM / FBK; kt++) {
            cp_wait<0>();
            __syncthreads();
            if (kt + 1 < DIM / FBK) stage(s ^ 1, kt + 1, Bw);

            const uint32_t so = s * FSTG;
            #pragma unroll
            for (int ks = 0; ks < 4; ks++) {
                const uint32_t ac = (uint32_t)(((ks * 2 + hc8) ^ xrow) << 4);
                uint32_t af[2][4], bf[2][4];
                ldsm_x4(af[0], arow + so + ac);
                ldsm_x4(af[1], arow + so + 16 * FROWB + ac);
                ldsm_x4(bf[0], brow + so + ac);
                ldsm_x4(bf[1], brow + so + 16 * FROWB + ac);
                #pragma unroll
                for (int mt = 0; mt < 2; mt++)
                    #pragma unroll
                    for (int p = 0; p < 2; p++) {
                        mma_f16_16x8x16(acc[mt][2 * p],
                                        af[mt][0], af[mt][1], af[mt][2], af[mt][3],
                                        bf[p][0], bf[p][2]);
                        mma_f16_16x8x16(acc[mt][2 * p + 1],
                                        af[mt][0], af[mt][1], af[mt][2], af[mt][3],
                                        bf[p][1], bf[p][3]);
                    }
            }
            s ^= 1;
        }

        // epilogue: acc -> fp16 smem tile (warp-private region, no barrier)
        __half* tp = (__half*)(smc + OFF_Q + ph * TILE_SZ);
        #pragma unroll
        for (int mt = 0; mt < 2; mt++) {
            const int r0 = warpM * 32 + mt * 16 + g;
            #pragma unroll
            for (int j = 0; j < 4; j++) {
                const int ncol = warpN * 32 + (j >> 1) * 16 + (j & 1) * 8 + 2 * tid4;
                *(__half2*)(tp + r0 * TSTRIDE + ncol) =
                    __floats2half2_rn(acc[mt][j][0], acc[mt][j][1]);
                *(__half2*)(tp + (r0 + 8) * TSTRIDE + ncol) =
                    __floats2half2_rn(acc[mt][j][2], acc[mt][j][3]);
            }
        }
    }
    __syncthreads();

    // ---- attention: 1 warp per (window, head), RoPE in registers ----
    {
        const int wi = wid;                         // window 0..7
        const int r16 = lane & 15, hc = (lane >> 4) * 8;
        const uint32_t base = sb + ((uint32_t)((wi * 16 + r16) * TSTRIDE + hc) << 1);
        const uint32_t qb = base + OFF_Q;
        const uint32_t kb = base + OFF_K;
        const uint32_t vb = base + OFF_V;

        uint32_t aq[4][4], bk[4][4];
        #pragma unroll
        for (int ks = 0; ks < 4; ks++) {
            ldsm_x4(aq[ks], qb + ks * 32);
            ldsm_x4(bk[ks], kb + ks * 32);
        }

        // in-register RoPE: (lane, reg j, half h) of fragment ks:
        //   pos = g + (j&1)*8,  d = ks*16 + (j>=2)*8 + 2*tid4 + h
        // pairs (d, d+32) = (frag[ks][j], frag[ks+2][j]), ks in {0,1}
        #pragma unroll
        for (int ks = 0; ks < 2; ks++) {
            #pragma unroll
            for (int j = 0; j < 4; j++) {
                const int pos = g + (j & 1) * 8;
                const int p0  = ks * 16 + ((j >> 1) & 1) * 8 + 2 * tid4;
                const float c0 = cs[pos * 32 + p0],     s0 = sn[pos * 32 + p0];
                const float c1 = cs[pos * 32 + p0 + 1], s1 = sn[pos * 32 + p0 + 1];
                {
                    float2 x = __half22float2(*(__half2*)&aq[ks][j]);
                    float2 y = __half22float2(*(__half2*)&aq[ks + 2][j]);
                    __half2 nx = __floats2half2_rn(x.x * c0 - y.x * s0,
                                                   x.y * c1 - y.y * s1);
                    __half2 ny = __floats2half2_rn(x.x * s0 + y.x * c0,
                                                   x.y * s1 + y.y * c1);
                    aq[ks][j]     = h2u(nx);
                    aq[ks + 2][j] = h2u(ny);
                }
                {
                    float2 x = __half22float2(*(__half2*)&bk[ks][j]);
                    float2 y = __half22float2(*(__half2*)&bk[ks + 2][j]);
                    __half2 nx = __floats2half2_rn(x.x * c0 - y.x * s0,
                                                   x.y * c1 - y.y * s1);
                    __half2 ny = __floats2half2_rn(x.x * s0 + y.x * c0,
                                                   x.y * s1 + y.y * c1);
                    bk[ks][j]     = h2u(nx);
                    bk[ks + 2][j] = h2u(ny);
                }
            }
        }

        float sc[2][4] = {};
        #pragma unroll
        for (int ks = 0; ks < 4; ks++) {
            mma_f16_16x8x16(sc[0], aq[ks][0], aq[ks][1], aq[ks][2], aq[ks][3],
                            bk[ks][0], bk[ks][2]);
            mma_f16_16x8x16(sc[1], aq[ks][0], aq[ks][1], aq[ks][2], aq[ks][3],
                            bk[ks][1], bk[ks][3]);
        }
        #pragma unroll
        for (int t2 = 0; t2 < 2; t2++)
            #pragma unroll
            for (int q = 0; q < 4; q++)
                sc[t2][q] *= 0.125f;

        float mA = fmaxf(fmaxf(sc[0][0], sc[0][1]), fmaxf(sc[1][0], sc[1][1]));
        float mB = fmaxf(fmaxf(sc[0][2], sc[0][3]), fmaxf(sc[1][2], sc[1][3]));
        mA = fmaxf(mA, __shfl_xor_sync(0xffffffffu, mA, 1));
        mA = fmaxf(mA, __shfl_xor_sync(0xffffffffu, mA, 2));
        mB = fmaxf(mB, __shfl_xor_sync(0xffffffffu, mB, 1));
        mB = fmaxf(mB, __shfl_xor_sync(0xffffffffu, mB, 2));
        float eA0 = expf(sc[0][0] - mA), eA1 = expf(sc[0][1] - mA);
        float eA2 = expf(sc[1][0] - mA), eA3 = expf(sc[1][1] - mA);
        float eB0 = expf(sc[0][2] - mB), eB1 = expf(sc[0][3] - mB);
        float eB2 = expf(sc[1][2] - mB), eB3 = expf(sc[1][3] - mB);
        float sA = eA0 + eA1 + eA2 + eA3;
        float sB = eB0 + eB1 + eB2 + eB3;
        sA += __shfl_xor_sync(0xffffffffu, sA, 1);
        sA += __shfl_xor_sync(0xffffffffu, sA, 2);
        sB += __shfl_xor_sync(0xffffffffu, sB, 1);
        sB += __shfl_xor_sync(0xffffffffu, sB, 2);
        const float iA = 1.f / sA, iB = 1.f / sB;

        const uint32_t p0 = h2u(__floats2half2_rn(eA0 * iA, eA1 * iA));
        const uint32_t p1 = h2u(__floats2half2_rn(eB0 * iB, eB1 * iB));
        const uint32_t p2 = h2u(__floats2half2_rn(eA2 * iA, eA3 * iA));
        const uint32_t p3 = h2u(__floats2half2_rn(eB2 * iB, eB3 * iB));

        float o[8][4] = {};
        #pragma unroll
        for (int nt = 0; nt < 4; nt++) {
            uint32_t bv[4];
            ldsm_x4_trans(bv, vb + nt * 32);
            mma_f16_16x8x16(o[2 * nt],     p0, p1, p2, p3, bv[0], bv[1]);
            mma_f16_16x8x16(o[2 * nt + 1], p0, p1, p2, p3, bv[2], bv[3]);
        }

        const size_t orow = (size_t)(bm + wi * 16 + g);
        #pragma unroll
        for (int nt = 0; nt < 4; nt++)
            #pragma unroll
            for (int sub = 0; sub < 2; sub++) {
                const int j = 2 * nt + sub;
                const int col = bn + nt * 16 + sub * 8 + 2 * tid4;
                *(__half2*)(g_attnh + orow * DIM + col) =
                    __floats2half2_rn(o[j][0], o[j][1]);
                *(__half2*)(g_attnh + (orow + 8) * DIM + col) =
                    __floats2half2_rn(o[j][2], o[j][3]);
            }
    }
}

// ---------------------------------------------------------------------------
// WO GEMM: CTA 256x128, BK=64, 512 threads, 16 warps of 64x32.
// SW128 XOR-swizzled staging. (unchanged R15)
// ---------------------------------------------------------------------------
constexpr int BM = 256, BN = 128, BK = 64;
constexpr int ROWB   = 128;
constexpr int A_SZ   = BM * ROWB;           // 32768
constexpr int B_SZ   = BN * ROWB;           // 16384
constexpr int STG_SZ = A_SZ + B_SZ;         // 49152
constexpr int GSMEM  = 2 * STG_SZ;          // 98304

__global__ __launch_bounds__(512, 1)
void gemm_wo(float* __restrict__ Cout)
{
    extern __shared__ uint32_t sm[];
    const uint32_t sbu = smem_u32(sm);
    const __half* A = g_attnh;
    const __half* B = g_woh;

    const int tid  = threadIdx.x;
    const int lane = tid & 31, wid = tid >> 5;
    const int g = lane >> 2, tid4 = lane & 3;
    const int warpM = wid & 3;
    const int warpN = wid >> 2;
    const int bm = blockIdx.y * BM, bn = blockIdx.x * BN;

    const int arow = tid >> 3, acc8 = tid & 7;
    const int swc  = acc8 ^ (arow & 7);
    const __half* Ag = A + (size_t)(bm + arow) * DIM + acc8 * 8;
    const __half* Bg = B + (size_t)(bn + arow) * DIM + acc8 * 8;
    const uint32_t sdA = sbu + arow * ROWB + swc * 16;
    const uint32_t sdB = sbu + A_SZ + arow * ROWB + swc * 16;

    auto stage = [&](int s, int kt) {
        const uint32_t so = s * STG_SZ;
        const size_t ko = (size_t)kt * BK;
        #pragma unroll
        for (int i = 0; i < 4; i++)
            cp_async16(sdA + so + i * 64 * ROWB, Ag + ko + (size_t)(64 * i) * DIM);
        #pragma unroll
        for (int i = 0; i < 2; i++)
            cp_async16(sdB + so + i * 64 * ROWB, Bg + ko + (size_t)(64 * i) * DIM);
    };

    const int xrow = lane & 7;
    const int hc8  = lane >> 4;
    const uint32_t arow0 = sbu + (uint32_t)(warpM * 64 + (lane & 15)) * ROWB;
    const uint32_t brow0 = sbu + A_SZ + (uint32_t)(warpN * 32 + (lane & 15)) * ROWB;

    float acc[4][4][4];
    #pragma unroll
    for (int i = 0; i < 4; i++)
        #pragma unroll
        for (int j = 0; j < 4; j++)
            #pragma unroll
            for (int q = 0; q < 4; q++)
                acc[i][j][q] = 0.f;

    stage(0, 0); cp_commit();

    const int NKT = DIM / BK;
    int s = 0;
    for (int kt = 0; kt < NKT; kt++) {
        cp_wait<0>();
        __syncthreads();
        if (kt + 1 < NKT) { stage(s ^ 1, kt + 1); cp_commit(); }

        const uint32_t so = s * STG_SZ;
        #pragma unroll
        for (int ks = 0; ks < 4; ks++) {
            const uint32_t ac = (uint32_t)(((ks * 2 + hc8) ^ xrow) << 4);
            uint32_t af[4][4], bf[2][4];
            #pragma unroll
            for (int mt = 0; mt < 4; mt++)
                ldsm_x4(af[mt], arow0 + so + mt * 16 * ROWB + ac);
            #pragma unroll
            for (int p = 0; p < 2; p++)
                ldsm_x4(bf[p], brow0 + so + p * 16 * ROWB + ac);
            #pragma unroll
            for (int mt = 0; mt < 4; mt++)
                #pragma unroll
                for (int p = 0; p < 2; p++) {
                    mma_f16_16x8x16(acc[mt][2 * p],
                                    af[mt][0], af[mt][1], af[mt][2], af[mt][3],
                                    bf[p][0], bf[p][2]);
                    mma_f16_16x8x16(acc[mt][2 * p + 1],
                                    af[mt][0], af[mt][1], af[mt][2], af[mt][3],
                                    bf[p][1], bf[p][3]);
                }
        }
        s ^= 1;
    }

    #pragma unroll
    for (int mt = 0; mt < 4; mt++) {
        const int r0 = bm + warpM * 64 + mt * 16 + g;
        #pragma unroll
        for (int j = 0; j < 4; j++) {
            const int ncol = bn + warpN * 32 + (j >> 1) * 16 + (j & 1) * 8;
            const float* a = acc[mt][j];
            *(float2*)(Cout + (size_t)r0 * DIM + ncol + 2 * tid4) =
                make_float2(a[0], a[1]);
            *(float2*)(Cout + (size_t)(r0 + 8) * DIM + ncol + 2 * tid4) =
                make_float2(a[2], a[3]);
        }
    }
}

// ---------------------------------------------------------------------------
// fp32 -> fp16 prepass: z 0..3 = quarters of x, z 4..7 = weights
// ---------------------------------------------------------------------------
__global__ void prep(const float4* __restrict__ x,
                     const float4* __restrict__ w0, const float4* __restrict__ w1,
                     const float4* __restrict__ w2, const float4* __restrict__ w3)
{
    const int z = blockIdx.z;
    const float4* src;
    uint2* dst;
    int n4;
    if (z < 4) {
        const int quarter = NTOK * DIM / 16;
        src = x + (size_t)z * quarter;
        dst = (uint2*)g_xh + (size_t)z * quarter;
        n4 = quarter;
    } else {
        src = (z == 4) ? w0 : (z == 5) ? w1 : (z == 6) ? w2 : w3;
        dst = (uint2*)((z == 4) ? g_wqh : (z == 5) ? g_wkh : (z == 6) ? g_wvh : g_woh);
        n4 = DIM * DIM / 4;
    }
    int i = blockIdx.x * blockDim.x + threadIdx.x;
    const int stride = gridDim.x * blockDim.x;
    for (; i < n4; i += stride) {
        float4 v = src[i];
        __half2 lo = __floats2half2_rn(v.x, v.y);
        __half2 hi = __floats2half2_rn(v.z, v.w);
        dst[i] = make_uint2(*(uint32_t*)&lo, *(uint32_t*)&hi);
    }
}

// ---------------------------------------------------------------------------
extern "C" void kernel_launch(void* const* d_in, const int* in_sizes, int n_in,
                              void* d_out, int out_size)
{
    const float* x    = (const float*)d_in[0];
    const float* rope = (const float*)d_in[1];
    const float* wq   = (const float*)d_in[2];
    const float* wk   = (const float*)d_in[3];
    const float* wv   = (const float*)d_in[4];
    const float* wo   = (const float*)d_in[5];
    float* out        = (float*)d_out;

    cudaFuncSetAttribute(fused_qkv_attn, cudaFuncAttributeMaxDynamicSharedMemorySize, FSMEM);
    cudaFuncSetAttribute(gemm_wo,        cudaFuncAttributeMaxDynamicSharedMemorySize, GSMEM);

    prep<<<dim3(256, 1, 8), 256>>>((const float4*)x, (const float4*)wq,
                                   (const float4*)wk, (const float4*)wv,
                                   (const float4*)wo);

    fused_qkv_attn<<<dim3(DIM / FBN, NTOK / FBM), 256, FSMEM>>>(rope);

    gemm_wo<<<dim3(DIM / BN, NTOK / BM), 512, GSMEM>>>(out);
}